// round 1
// baseline (speedup 1.0000x reference)
#include <cuda_runtime.h>
#include <math.h>

#define B_  128
#define LQ_ 32
#define LD_ 512
#define H_  768
#define C_  128

// Scratch (allocation-free rule: __device__ globals)
__device__ float g_dvecs[B_ * LD_ * C_];   // 33.5 MB
__device__ float g_qvecs[B_ * LQ_ * C_];   // 2 MB

// ---------------------------------------------------------------------------
// Projection GEMM: out[row, c] = X[row, :H] @ W[:, c] + b_comp[c], fused epilogue.
// DOC:  importance = relu(dot(row_vec, w_stop) + b_stop); out *= importance * dm[row]
// !DOC: out *= qm[row]
// Block: 64 rows x 128 cols (full C), 256 threads, each thread 4x8 outputs.
// ---------------------------------------------------------------------------
template <bool DOC>
__global__ void __launch_bounds__(256) gemm_comp(
    const float* __restrict__ X,
    const float* __restrict__ W,
    const float* __restrict__ bcomp,
    const float* __restrict__ wstop,
    const float* __restrict__ bstop,
    const int*   __restrict__ mask)
{
    __shared__ float As[32][65];    // [k][row], padded
    __shared__ float Bs[32][132];   // [k][c], padded

    const int t    = threadIdx.x;
    const int row0 = blockIdx.x * 64;
    const int ty   = t >> 4;        // 0..15 -> 4 rows each
    const int tx   = t & 15;        // 0..15 -> 8 cols each

    float acc[4][8];
#pragma unroll
    for (int i = 0; i < 4; i++)
#pragma unroll
        for (int j = 0; j < 8; j++) acc[i][j] = 0.f;

    for (int kt = 0; kt < H_; kt += 32) {
        // Load A tile: 64 rows x 32 k = 512 float4 (2 per thread), transpose to As[k][row]
#pragma unroll
        for (int u = 0; u < 2; u++) {
            int i  = t + u * 256;
            int r  = i >> 3;
            int kq = (i & 7) * 4;
            float4 v = *(const float4*)(X + (size_t)(row0 + r) * H_ + kt + kq);
            As[kq + 0][r] = v.x; As[kq + 1][r] = v.y;
            As[kq + 2][r] = v.z; As[kq + 3][r] = v.w;
        }
        // Load B tile: 32 k x 128 c = 1024 float4 (4 per thread)
#pragma unroll
        for (int u = 0; u < 4; u++) {
            int i  = t + u * 256;
            int k  = i >> 5;
            int cq = (i & 31) * 4;
            *(float4*)&Bs[k][cq] = *(const float4*)(W + (size_t)(kt + k) * C_ + cq);
        }
        __syncthreads();

#pragma unroll
        for (int k = 0; k < 32; k++) {
            float a[4];
#pragma unroll
            for (int i = 0; i < 4; i++) a[i] = As[k][ty * 4 + i];
            float4 b0 = *(float4*)&Bs[k][tx * 8];
            float4 b1 = *(float4*)&Bs[k][tx * 8 + 4];
            float bv[8] = {b0.x, b0.y, b0.z, b0.w, b1.x, b1.y, b1.z, b1.w};
#pragma unroll
            for (int i = 0; i < 4; i++)
#pragma unroll
                for (int j = 0; j < 8; j++) acc[i][j] += a[i] * bv[j];
        }
        __syncthreads();
    }

    // bias
    float bc[8];
#pragma unroll
    for (int j = 0; j < 8; j++) bc[j] = bcomp[tx * 8 + j];
#pragma unroll
    for (int i = 0; i < 4; i++)
#pragma unroll
        for (int j = 0; j < 8; j++) acc[i][j] += bc[j];

    if (DOC) {
        float ws[8];
#pragma unroll
        for (int j = 0; j < 8; j++) ws[j] = wstop[tx * 8 + j];
        const float bst = bstop[0];
#pragma unroll
        for (int i = 0; i < 4; i++) {
            // importance dot across the 16-lane tx group (covers all 128 C)
            float p = 0.f;
#pragma unroll
            for (int j = 0; j < 8; j++) p += acc[i][j] * ws[j];
#pragma unroll
            for (int m = 8; m >= 1; m >>= 1) p += __shfl_xor_sync(0xffffffffu, p, m);
            float imp = fmaxf(p + bst, 0.f);
            int row   = row0 + ty * 4 + i;
            float s   = imp * (float)mask[row];
#pragma unroll
            for (int j = 0; j < 8; j++) acc[i][j] *= s;
            float4 v0 = make_float4(acc[i][0], acc[i][1], acc[i][2], acc[i][3]);
            float4 v1 = make_float4(acc[i][4], acc[i][5], acc[i][6], acc[i][7]);
            *(float4*)(g_dvecs + (size_t)row * C_ + tx * 8)     = v0;
            *(float4*)(g_dvecs + (size_t)row * C_ + tx * 8 + 4) = v1;
        }
    } else {
#pragma unroll
        for (int i = 0; i < 4; i++) {
            int row = row0 + ty * 4 + i;
            float s = (float)mask[row];
            float4 v0 = make_float4(acc[i][0] * s, acc[i][1] * s, acc[i][2] * s, acc[i][3] * s);
            float4 v1 = make_float4(acc[i][4] * s, acc[i][5] * s, acc[i][6] * s, acc[i][7] * s);
            *(float4*)(g_qvecs + (size_t)row * C_ + tx * 8)     = v0;
            *(float4*)(g_qvecs + (size_t)row * C_ + tx * 8 + 4) = v1;
        }
    }
}

// ---------------------------------------------------------------------------
// Per-batch scoring: cls dot + max-over-k of q_vecs @ d_vecs^T (dm-masked),
// summed over qm-valid q rows, merged with sigmoid(score_merger).
// One block per batch, 256 threads. Thread = (qy,kx): 2 q-rows x 2 k-rows.
// ---------------------------------------------------------------------------
__global__ void __launch_bounds__(256) score_kernel(
    const float* __restrict__ qh,
    const float* __restrict__ dhid,
    const int*   __restrict__ qmask,
    const int*   __restrict__ dmask,
    const float* __restrict__ merger,
    float*       __restrict__ out)
{
    const int b = blockIdx.x;
    const int t = threadIdx.x;

    __shared__ float qs[32][132];
    __shared__ float ds[32][132];
    __shared__ float red[256];
    __shared__ float redm[32][16];
    __shared__ int   dmch[32];
    __shared__ float s_cls;

    // --- CLS score: dot(query_hidden[b,0,:], doc_hidden[b,0,:]) over H ---
    {
        const float* qp = qh   + (size_t)b * LQ_ * H_;
        const float* dp = dhid + (size_t)b * LD_ * H_;
        float p = 0.f;
        for (int h = t; h < H_; h += 256) p += qp[h] * dp[h];
        red[t] = p;
        __syncthreads();
        for (int s = 128; s > 0; s >>= 1) {
            if (t < s) red[t] += red[t + s];
            __syncthreads();
        }
        if (t == 0) s_cls = red[0];
    }

    // --- Load q_vecs [32 x 128] ---
#pragma unroll
    for (int u = 0; u < 4; u++) {
        int i  = t + u * 256;
        int q  = i >> 5;
        int cq = (i & 31) * 4;
        *(float4*)&qs[q][cq] =
            *(const float4*)(g_qvecs + (size_t)b * LQ_ * C_ + (size_t)q * C_ + cq);
    }

    const int qy = t >> 4;   // 0..15 -> q rows {2qy, 2qy+1}
    const int kx = t & 15;   // 0..15 -> k rows {2kx, 2kx+1} within chunk
    float mx0 = -1000.f, mx1 = -1000.f;

    for (int ch = 0; ch < 16; ch++) {
        const int k0 = ch * 32;
        __syncthreads();   // also covers qs stores (first iter) / ds reuse (later)
#pragma unroll
        for (int u = 0; u < 4; u++) {
            int i  = t + u * 256;
            int k  = i >> 5;
            int cq = (i & 31) * 4;
            *(float4*)&ds[k][cq] = *(const float4*)(
                g_dvecs + (size_t)b * LD_ * C_ + (size_t)(k0 + k) * C_ + cq);
        }
        if (t < 32) dmch[t] = dmask[b * LD_ + k0 + t];
        __syncthreads();

        float a00 = 0.f, a01 = 0.f, a10 = 0.f, a11 = 0.f;
#pragma unroll
        for (int c = 0; c < C_; c += 4) {
            float4 q0 = *(float4*)&qs[qy * 2 + 0][c];
            float4 q1 = *(float4*)&qs[qy * 2 + 1][c];
            float4 d0 = *(float4*)&ds[kx * 2 + 0][c];
            float4 d1 = *(float4*)&ds[kx * 2 + 1][c];
            a00 += q0.x * d0.x; a00 += q0.y * d0.y; a00 += q0.z * d0.z; a00 += q0.w * d0.w;
            a01 += q0.x * d1.x; a01 += q0.y * d1.y; a01 += q0.z * d1.z; a01 += q0.w * d1.w;
            a10 += q1.x * d0.x; a10 += q1.y * d0.y; a10 += q1.z * d0.z; a10 += q1.w * d0.w;
            a11 += q1.x * d1.x; a11 += q1.y * d1.y; a11 += q1.z * d1.z; a11 += q1.w * d1.w;
        }
        if (dmch[kx * 2 + 0]) { mx0 = fmaxf(mx0, a00); mx1 = fmaxf(mx1, a10); }
        if (dmch[kx * 2 + 1]) { mx0 = fmaxf(mx0, a01); mx1 = fmaxf(mx1, a11); }
    }

    redm[qy * 2 + 0][kx] = mx0;
    redm[qy * 2 + 1][kx] = mx1;
    __syncthreads();

    if (t < 32) {
        float m = -1000.f;
#pragma unroll
        for (int x = 0; x < 16; x++) m = fmaxf(m, redm[t][x]);
        float term = qmask[b * LQ_ + t] ? m : 0.f;
#pragma unroll
        for (int o = 16; o >= 1; o >>= 1) term += __shfl_xor_sync(0xffffffffu, term, o);
        if (t == 0) {
            float w   = 1.f / (1.f + expf(-merger[0]));
            float cls = s_cls * w;
            float ts  = term * (1.f - w);
            out[b]          = cls + ts;
            out[B_ + b]     = cls;
            out[2 * B_ + b] = ts;
        }
    }
}

extern "C" void kernel_launch(void* const* d_in, const int* in_sizes, int n_in,
                              void* d_out, int out_size)
{
    const float* query_hidden = (const float*)d_in[0];
    const float* doc_hidden   = (const float*)d_in[1];
    const int*   query_mask   = (const int*)  d_in[2];
    const int*   doc_mask     = (const int*)  d_in[3];
    const float* W_comp       = (const float*)d_in[4];
    const float* b_comp       = (const float*)d_in[5];
    const float* w_stop       = (const float*)d_in[6];
    const float* b_stop       = (const float*)d_in[7];
    const float* score_merger = (const float*)d_in[8];
    float* out = (float*)d_out;

    // Doc projection + importance + dm mask -> g_dvecs
    gemm_comp<true><<<(B_ * LD_) / 64, 256>>>(
        doc_hidden, W_comp, b_comp, w_stop, b_stop, doc_mask);
    // Query projection + qm mask -> g_qvecs
    gemm_comp<false><<<(B_ * LQ_) / 64, 256>>>(
        query_hidden, W_comp, b_comp, w_stop, b_stop, query_mask);
    // Per-batch scoring
    score_kernel<<<B_, 256>>>(
        query_hidden, doc_hidden, query_mask, doc_mask, score_merger, out);
}

// round 3
// speedup vs baseline: 1.9791x; 1.9791x over previous
#include <cuda_runtime.h>
#include <math.h>
#include <stdint.h>

#define B_  128
#define LQ_ 32
#define LD_ 512
#define H_  768
#define C_  128
#define KCH 32
#define NCH (H_ / KCH)   // 24 K-chunks
#define APAD 136

// Scratch (__device__ globals: allocation-free rule)
__device__ float g_dvecs[B_ * LD_ * C_];   // 33.5 MB
__device__ float g_qvecs[B_ * LQ_ * C_];   // 2 MB
__device__ float g_Wt[C_ * H_];            // W_comp transposed, tf32-rounded

__device__ __forceinline__ float tf32_rna(float x) {
    uint32_t u;
    asm("cvt.rna.tf32.f32 %0, %1;" : "=r"(u) : "f"(x));
    return __uint_as_float(u);
}

__device__ __forceinline__ void mma_tf32(float c[4], uint32_t a0, uint32_t a1,
                                         uint32_t a2, uint32_t a3,
                                         uint32_t b0, uint32_t b1) {
    asm volatile(
        "mma.sync.aligned.m16n8k8.row.col.f32.tf32.tf32.f32 "
        "{%0,%1,%2,%3}, {%4,%5,%6,%7}, {%8,%9}, {%0,%1,%2,%3};"
        : "+f"(c[0]), "+f"(c[1]), "+f"(c[2]), "+f"(c[3])
        : "r"(a0), "r"(a1), "r"(a2), "r"(a3), "r"(b0), "r"(b1));
}

// ---------------------------------------------------------------------------
// Prep: transpose W_comp [H,C] -> g_Wt [C,H] (K-major), rounded to tf32
// ---------------------------------------------------------------------------
__global__ void prep_w(const float* __restrict__ W) {
    int idx = blockIdx.x * 256 + threadIdx.x;
    if (idx < H_ * C_) {
        int k = idx / C_, c = idx % C_;
        g_Wt[c * H_ + k] = tf32_rna(W[idx]);
    }
}

// ---------------------------------------------------------------------------
// Projection GEMM via mma.sync tf32: 128 rows x 128 cols per CTA, K=768.
// 8 warps in 4(m) x 2(n): warp tile m32 x n64 (2 mtiles x 8 ntiles of 16x8).
// DOC: fused importance gating + dm mask -> g_dvecs; else qm mask -> g_qvecs.
// ---------------------------------------------------------------------------
template <bool DOC>
__global__ void __launch_bounds__(256, 2) gemm_tc(
    const float* __restrict__ X,
    const float* __restrict__ bcomp,
    const float* __restrict__ wstop,
    const float* __restrict__ bstop,
    const int*   __restrict__ mask)
{
    __shared__ float As[KCH][APAD];   // [k][row]
    __shared__ float Bs[KCH][APAD];   // [k][col]

    const int t    = threadIdx.x;
    const int lane = t & 31;
    const int w    = t >> 5;
    const int wm   = w >> 1;          // 0..3
    const int wn   = w & 1;           // 0..1
    const int g    = lane >> 2;       // 0..7
    const int tig  = lane & 3;        // 0..3
    const int Rl   = wm * 32;         // local row base
    const int Cl   = wn * 64;         // local col base
    const int row0 = blockIdx.x * 128;

    // staging coords: 4 waves, wave u: rows (lane + 32u), k-quad = 4*warp
    const int s_r  = lane;
    const int s_kq = w * 4;

    float acc[2][8][4];
#pragma unroll
    for (int mt = 0; mt < 2; mt++)
#pragma unroll
        for (int nt = 0; nt < 8; nt++)
#pragma unroll
            for (int x = 0; x < 4; x++) acc[mt][nt][x] = 0.f;

    for (int ch = 0; ch < NCH; ch++) {
        const int kt = ch * KCH;
        // Stage A: 128 rows x 32 k, tf32-rounded, transposed to As[k][row]
#pragma unroll
        for (int u = 0; u < 4; u++) {
            int r = s_r + u * 32;
            float4 v = *(const float4*)(X + (size_t)(row0 + r) * H_ + kt + s_kq);
            As[s_kq + 0][r] = tf32_rna(v.x);
            As[s_kq + 1][r] = tf32_rna(v.y);
            As[s_kq + 2][r] = tf32_rna(v.z);
            As[s_kq + 3][r] = tf32_rna(v.w);
        }
        // Stage B: 128 cols x 32 k from g_Wt (pre-rounded), to Bs[k][col]
#pragma unroll
        for (int u = 0; u < 4; u++) {
            int c = s_r + u * 32;
            float4 v = *(const float4*)(g_Wt + (size_t)c * H_ + kt + s_kq);
            Bs[s_kq + 0][c] = v.x;
            Bs[s_kq + 1][c] = v.y;
            Bs[s_kq + 2][c] = v.z;
            Bs[s_kq + 3][c] = v.w;
        }
        __syncthreads();

#pragma unroll
        for (int ks = 0; ks < 4; ks++) {
            const int k0 = ks * 8;
            uint32_t a[2][4];
#pragma unroll
            for (int mt = 0; mt < 2; mt++) {
                int r = Rl + mt * 16 + g;
                a[mt][0] = __float_as_uint(As[k0 + tig][r]);
                a[mt][1] = __float_as_uint(As[k0 + tig][r + 8]);
                a[mt][2] = __float_as_uint(As[k0 + tig + 4][r]);
                a[mt][3] = __float_as_uint(As[k0 + tig + 4][r + 8]);
            }
            uint32_t b[8][2];
#pragma unroll
            for (int nt = 0; nt < 8; nt++) {
                int c = Cl + nt * 8 + g;
                b[nt][0] = __float_as_uint(Bs[k0 + tig][c]);
                b[nt][1] = __float_as_uint(Bs[k0 + tig + 4][c]);
            }
#pragma unroll
            for (int nt = 0; nt < 8; nt++) {
                mma_tf32(acc[0][nt], a[0][0], a[0][1], a[0][2], a[0][3],
                         b[nt][0], b[nt][1]);
                mma_tf32(acc[1][nt], a[1][0], a[1][1], a[1][2], a[1][3],
                         b[nt][0], b[nt][1]);
            }
        }
        __syncthreads();
    }

    // ---- Epilogue ----
    // Per-lane column constants
    float bb[8][2];
#pragma unroll
    for (int nt = 0; nt < 8; nt++) {
        int c0 = Cl + nt * 8 + 2 * tig;
        bb[nt][0] = bcomp[c0];
        bb[nt][1] = bcomp[c0 + 1];
    }

    float (*spart)[2] = (float(*)[2])As;   // 128 x 2 partials
    float* sscale     = (float*)Bs;        // 128 scales

    if (DOC) {
        float ws[8][2];
#pragma unroll
        for (int nt = 0; nt < 8; nt++) {
            int c0 = Cl + nt * 8 + 2 * tig;
            ws[nt][0] = wstop[c0];
            ws[nt][1] = wstop[c0 + 1];
        }
        float p[2][2] = {{0.f, 0.f}, {0.f, 0.f}};
#pragma unroll
        for (int mt = 0; mt < 2; mt++)
#pragma unroll
            for (int nt = 0; nt < 8; nt++) {
                p[mt][0] += (acc[mt][nt][0] + bb[nt][0]) * ws[nt][0]
                          + (acc[mt][nt][1] + bb[nt][1]) * ws[nt][1];
                p[mt][1] += (acc[mt][nt][2] + bb[nt][0]) * ws[nt][0]
                          + (acc[mt][nt][3] + bb[nt][1]) * ws[nt][1];
            }
#pragma unroll
        for (int mt = 0; mt < 2; mt++)
#pragma unroll
            for (int h = 0; h < 2; h++) {
                float v = p[mt][h];
                v += __shfl_xor_sync(0xffffffffu, v, 1);
                v += __shfl_xor_sync(0xffffffffu, v, 2);
                p[mt][h] = v;
            }
        if (tig == 0) {
#pragma unroll
            for (int mt = 0; mt < 2; mt++)
#pragma unroll
                for (int h = 0; h < 2; h++)
                    spart[Rl + mt * 16 + g + 8 * h][wn] = p[mt][h];
        }
        __syncthreads();
        if (t < 128) {
            float pp = spart[t][0] + spart[t][1] + bstop[0];
            sscale[t] = fmaxf(pp, 0.f) * (float)mask[row0 + t];
        }
        __syncthreads();
    } else {
        __syncthreads();
        if (t < 128) sscale[t] = (float)mask[row0 + t];
        __syncthreads();
    }

    float* OUT = DOC ? g_dvecs : g_qvecs;
#pragma unroll
    for (int mt = 0; mt < 2; mt++)
#pragma unroll
        for (int h = 0; h < 2; h++) {
            int lrow = Rl + mt * 16 + g + 8 * h;
            float s  = sscale[lrow];
            int row  = row0 + lrow;
#pragma unroll
            for (int nt = 0; nt < 8; nt++) {
                int c0 = Cl + nt * 8 + 2 * tig;
                float2 v;
                v.x = (acc[mt][nt][2 * h + 0] + bb[nt][0]) * s;
                v.y = (acc[mt][nt][2 * h + 1] + bb[nt][1]) * s;
                *(float2*)(OUT + (size_t)row * C_ + c0) = v;
            }
        }
}

// ---------------------------------------------------------------------------
// Per-batch scoring. 256 threads. Tile 4q x 4k per thread, k-chunk = 128.
// ---------------------------------------------------------------------------
#define DS_PAD 132
#define SCORE_SMEM ((32 * 128 + 128 * DS_PAD + 32 * 32) * 4 + 128 * 4)

__global__ void __launch_bounds__(256) score_kernel(
    const float* __restrict__ qh,
    const float* __restrict__ dhid,
    const int*   __restrict__ qmask,
    const int*   __restrict__ dmask,
    const float* __restrict__ merger,
    float*       __restrict__ out)
{
    extern __shared__ float sm[];
    float* qs   = sm;                         // 32 * 128
    float* ds   = sm + 32 * 128;              // 128 * DS_PAD
    float* redm = ds + 128 * DS_PAD;          // 32 * 32
    int*   dmch = (int*)(redm + 32 * 32);     // 128

    __shared__ float s_red[256];
    __shared__ float s_cls;

    const int b = blockIdx.x;
    const int t = threadIdx.x;

    // --- CLS dot over H ---
    {
        const float* qp = qh   + (size_t)b * LQ_ * H_;
        const float* dp = dhid + (size_t)b * LD_ * H_;
        float p = 0.f;
        for (int h = t; h < H_; h += 256) p += qp[h] * dp[h];
        s_red[t] = p;
        __syncthreads();
        for (int s = 128; s > 0; s >>= 1) {
            if (t < s) s_red[t] += s_red[t + s];
            __syncthreads();
        }
        if (t == 0) s_cls = s_red[0];
    }

    // --- Load q_vecs [32 x 128] ---
#pragma unroll
    for (int u = 0; u < 4; u++) {
        int i  = t + u * 256;
        int q  = i >> 5;
        int cq = (i & 31) * 4;
        *(float4*)&qs[q * 128 + cq] =
            *(const float4*)(g_qvecs + (size_t)b * LQ_ * C_ + (size_t)q * C_ + cq);
    }

    const int qg = t >> 5;   // q rows: qg + 8*i
    const int kg = t & 31;   // k rows: base + kg + 32*j
    float mx[4] = {-1000.f, -1000.f, -1000.f, -1000.f};

    for (int ch = 0; ch < 4; ch++) {
        const int k0 = ch * 128;
        __syncthreads();
#pragma unroll
        for (int u = 0; u < 16; u++) {
            int i  = t + u * 256;
            int k  = i >> 5;
            int cq = (i & 31) * 4;
            *(float4*)&ds[k * DS_PAD + cq] = *(const float4*)(
                g_dvecs + (size_t)b * LD_ * C_ + (size_t)(k0 + k) * C_ + cq);
        }
        if (t < 128) dmch[t] = dmask[b * LD_ + k0 + t];
        __syncthreads();

        float acc[4][4];
#pragma unroll
        for (int i = 0; i < 4; i++)
#pragma unroll
            for (int j = 0; j < 4; j++) acc[i][j] = 0.f;

#pragma unroll 4
        for (int c = 0; c < C_; c += 4) {
            float4 qv[4], dv[4];
#pragma unroll
            for (int i = 0; i < 4; i++) qv[i] = *(float4*)&qs[(qg + 8 * i) * 128 + c];
#pragma unroll
            for (int j = 0; j < 4; j++) dv[j] = *(float4*)&ds[(kg + 32 * j) * DS_PAD + c];
#pragma unroll
            for (int i = 0; i < 4; i++)
#pragma unroll
                for (int j = 0; j < 4; j++) {
                    acc[i][j] += qv[i].x * dv[j].x;
                    acc[i][j] += qv[i].y * dv[j].y;
                    acc[i][j] += qv[i].z * dv[j].z;
                    acc[i][j] += qv[i].w * dv[j].w;
                }
        }
#pragma unroll
        for (int j = 0; j < 4; j++) {
            if (dmch[kg + 32 * j]) {
#pragma unroll
                for (int i = 0; i < 4; i++) mx[i] = fmaxf(mx[i], acc[i][j]);
            }
        }
    }

    __syncthreads();
#pragma unroll
    for (int i = 0; i < 4; i++) redm[(qg + 8 * i) * 32 + kg] = mx[i];
    __syncthreads();

    if (t < 32) {
        float m = -1000.f;
#pragma unroll
        for (int x = 0; x < 32; x++) m = fmaxf(m, redm[t * 32 + x]);
        float term = qmask[b * LQ_ + t] ? m : 0.f;
#pragma unroll
        for (int o = 16; o >= 1; o >>= 1) term += __shfl_xor_sync(0xffffffffu, term, o);
        if (t == 0) {
            float w   = 1.f / (1.f + expf(-merger[0]));
            float cls = s_cls * w;
            float ts  = term * (1.f - w);
            out[b]          = cls + ts;
            out[B_ + b]     = cls;
            out[2 * B_ + b] = ts;
        }
    }
}

extern "C" void kernel_launch(void* const* d_in, const int* in_sizes, int n_in,
                              void* d_out, int out_size)
{
    const float* query_hidden = (const float*)d_in[0];
    const float* doc_hidden   = (const float*)d_in[1];
    const int*   query_mask   = (const int*)  d_in[2];
    const int*   doc_mask     = (const int*)  d_in[3];
    const float* W_comp       = (const float*)d_in[4];
    const float* b_comp       = (const float*)d_in[5];
    const float* w_stop       = (const float*)d_in[6];
    const float* b_stop       = (const float*)d_in[7];
    const float* score_merger = (const float*)d_in[8];
    float* out = (float*)d_out;

    cudaFuncSetAttribute(score_kernel,
                         cudaFuncAttributeMaxDynamicSharedMemorySize, SCORE_SMEM);

    prep_w<<<(H_ * C_ + 255) / 256, 256>>>(W_comp);
    gemm_tc<true><<<(B_ * LD_) / 128, 256>>>(
        doc_hidden, b_comp, w_stop, b_stop, doc_mask);
    gemm_tc<false><<<(B_ * LQ_) / 128, 256>>>(
        query_hidden, b_comp, w_stop, b_stop, query_mask);
    score_kernel<<<B_, 256, SCORE_SMEM>>>(
        query_hidden, doc_hidden, query_mask, doc_mask, score_merger, out);
}

// round 4
// speedup vs baseline: 3.8263x; 1.9333x over previous
#include <cuda_runtime.h>
#include <math.h>
#include <stdint.h>

#define B_  128
#define LQ_ 32
#define LD_ 512
#define H_  768
#define C_  128
#define KCH 32
#define NCH (H_ / KCH)   // 24 K-chunks
#define AP  36           // [row][k] pad

// Scratch (__device__ globals: allocation-free rule)
__device__ float g_dvecs[B_ * LD_ * C_];   // 33.5 MB
__device__ float g_qvecs[B_ * LQ_ * C_];   // 2 MB
__device__ float g_Wt[C_ * H_];            // W_comp transposed, tf32-rounded

__device__ __forceinline__ float tf32_rna(float x) {
    uint32_t u;
    asm("cvt.rna.tf32.f32 %0, %1;" : "=r"(u) : "f"(x));
    return __uint_as_float(u);
}
__device__ __forceinline__ uint32_t smem_u32(const void* p) {
    uint32_t a;
    asm("{ .reg .u64 t; cvta.to.shared.u64 t, %1; cvt.u32.u64 %0, t; }"
        : "=r"(a) : "l"(p));
    return a;
}
__device__ __forceinline__ void cp16(void* dst, const void* src) {
    asm volatile("cp.async.cg.shared.global [%0], [%1], 16;"
                 :: "r"(smem_u32(dst)), "l"(src));
}
#define CP_COMMIT() asm volatile("cp.async.commit_group;" ::: "memory")
#define CP_WAIT0()  asm volatile("cp.async.wait_group 0;" ::: "memory")

__device__ __forceinline__ void mma_tf32(float c[4], uint32_t a0, uint32_t a1,
                                         uint32_t a2, uint32_t a3,
                                         uint32_t b0, uint32_t b1) {
    asm volatile(
        "mma.sync.aligned.m16n8k8.row.col.f32.tf32.tf32.f32 "
        "{%0,%1,%2,%3}, {%4,%5,%6,%7}, {%8,%9}, {%0,%1,%2,%3};"
        : "+f"(c[0]), "+f"(c[1]), "+f"(c[2]), "+f"(c[3])
        : "r"(a0), "r"(a1), "r"(a2), "r"(a3), "r"(b0), "r"(b1));
}

// ---------------------------------------------------------------------------
// Prep: transpose W_comp [H,C] -> g_Wt [C,H] (K-major), rounded to tf32
// ---------------------------------------------------------------------------
__global__ void prep_w(const float* __restrict__ W) {
    int idx = blockIdx.x * 256 + threadIdx.x;
    if (idx < H_ * C_) {
        int k = idx / C_, c = idx % C_;
        g_Wt[c * H_ + k] = tf32_rna(W[idx]);
    }
}

// ---------------------------------------------------------------------------
// Pipelined projection GEMM (mma.sync tf32): 128x128 tile/CTA, K=768.
// A: register double-buffer (LDG.128 prefetch, cvt.rna, STS). B: cp.async
// double-buffered smem (pre-rounded g_Wt, L2-resident).
// DOC: fused importance gating + dm mask -> g_dvecs; else qm -> g_qvecs.
// ---------------------------------------------------------------------------
#define GEMM_SMEM (3 * 128 * AP * 4)

template <bool DOC>
__global__ void __launch_bounds__(256, 2) gemm_tc(
    const float* __restrict__ X,
    const float* __restrict__ bcomp,
    const float* __restrict__ wstop,
    const float* __restrict__ bstop,
    const int*   __restrict__ mask)
{
    extern __shared__ float smg[];
    float (*As)[AP]      = (float(*)[AP])smg;                    // [128][AP]
    float (*Bs)[128][AP] = (float(*)[128][AP])(smg + 128 * AP);  // [2][128][AP]

    const int t    = threadIdx.x;
    const int lane = t & 31;
    const int w    = t >> 5;
    const int wm   = w >> 1, wn = w & 1;
    const int g    = lane >> 2, tig = lane & 3;
    const int Rl   = wm * 32, Cl = wn * 64;
    const int row0 = blockIdx.x * 128;

    const int sr  = t >> 3;         // staging row base (0..31)
    const int skq = (t & 7) * 4;    // staging col (floats)

    const float* Xp = X    + (size_t)(row0 + sr) * H_ + skq;
    const float* Wp = g_Wt + (size_t)sr * H_ + skq;

    float4 areg[4];
    float acc[2][8][4];
#pragma unroll
    for (int mt = 0; mt < 2; mt++)
#pragma unroll
        for (int nt = 0; nt < 8; nt++)
#pragma unroll
            for (int x = 0; x < 4; x++) acc[mt][nt][x] = 0.f;

    // ---- prologue: chunk 0 ----
#pragma unroll
    for (int u = 0; u < 4; u++)
        areg[u] = *(const float4*)(Xp + (size_t)(32 * u) * H_);
#pragma unroll
    for (int u = 0; u < 4; u++)
        cp16(&Bs[0][sr + 32 * u][skq], Wp + (size_t)(32 * u) * H_);
    CP_COMMIT();
#pragma unroll
    for (int u = 0; u < 4; u++) {
        float4 v = areg[u];
        float4 r;
        r.x = tf32_rna(v.x); r.y = tf32_rna(v.y);
        r.z = tf32_rna(v.z); r.w = tf32_rna(v.w);
        *(float4*)&As[sr + 32 * u][skq] = r;
    }
    CP_WAIT0();
    __syncthreads();

    for (int ch = 0; ch < NCH; ch++) {
        const bool more = (ch + 1) < NCH;
        const int  ktn  = (ch + 1) * KCH;
        if (more) {
#pragma unroll
            for (int u = 0; u < 4; u++)
                areg[u] = *(const float4*)(Xp + (size_t)(32 * u) * H_ + ktn);
#pragma unroll
            for (int u = 0; u < 4; u++)
                cp16(&Bs[(ch + 1) & 1][sr + 32 * u][skq],
                     Wp + (size_t)(32 * u) * H_ + ktn);
            CP_COMMIT();
        }

        const int p = ch & 1;
#pragma unroll
        for (int ks = 0; ks < 4; ks++) {
            const int k0 = ks * 8;
            uint32_t a[2][4];
#pragma unroll
            for (int mt = 0; mt < 2; mt++) {
                int r = Rl + mt * 16 + g;
                a[mt][0] = __float_as_uint(As[r][k0 + tig]);
                a[mt][1] = __float_as_uint(As[r + 8][k0 + tig]);
                a[mt][2] = __float_as_uint(As[r][k0 + tig + 4]);
                a[mt][3] = __float_as_uint(As[r + 8][k0 + tig + 4]);
            }
#pragma unroll
            for (int nt = 0; nt < 8; nt++) {
                int c = Cl + nt * 8 + g;
                uint32_t b0 = __float_as_uint(Bs[p][c][k0 + tig]);
                uint32_t b1 = __float_as_uint(Bs[p][c][k0 + tig + 4]);
                mma_tf32(acc[0][nt], a[0][0], a[0][1], a[0][2], a[0][3], b0, b1);
                mma_tf32(acc[1][nt], a[1][0], a[1][1], a[1][2], a[1][3], b0, b1);
            }
        }
        __syncthreads();
        if (more) {
#pragma unroll
            for (int u = 0; u < 4; u++) {
                float4 v = areg[u];
                float4 r;
                r.x = tf32_rna(v.x); r.y = tf32_rna(v.y);
                r.z = tf32_rna(v.z); r.w = tf32_rna(v.w);
                *(float4*)&As[sr + 32 * u][skq] = r;
            }
            CP_WAIT0();
        }
        __syncthreads();
    }

    // ---- Epilogue ----
    float bb[8][2];
#pragma unroll
    for (int nt = 0; nt < 8; nt++) {
        int c0 = Cl + nt * 8 + 2 * tig;
        bb[nt][0] = bcomp[c0];
        bb[nt][1] = bcomp[c0 + 1];
    }

    float (*spart)[2] = (float(*)[2])smg;   // 128 x 2 partials
    float* sscale     = smg + 256;          // 128 scales

    if (DOC) {
        float ws[8][2];
#pragma unroll
        for (int nt = 0; nt < 8; nt++) {
            int c0 = Cl + nt * 8 + 2 * tig;
            ws[nt][0] = wstop[c0];
            ws[nt][1] = wstop[c0 + 1];
        }
        float p[2][2] = {{0.f, 0.f}, {0.f, 0.f}};
#pragma unroll
        for (int mt = 0; mt < 2; mt++)
#pragma unroll
            for (int nt = 0; nt < 8; nt++) {
                p[mt][0] += (acc[mt][nt][0] + bb[nt][0]) * ws[nt][0]
                          + (acc[mt][nt][1] + bb[nt][1]) * ws[nt][1];
                p[mt][1] += (acc[mt][nt][2] + bb[nt][0]) * ws[nt][0]
                          + (acc[mt][nt][3] + bb[nt][1]) * ws[nt][1];
            }
#pragma unroll
        for (int mt = 0; mt < 2; mt++)
#pragma unroll
            for (int h = 0; h < 2; h++) {
                float v = p[mt][h];
                v += __shfl_xor_sync(0xffffffffu, v, 1);
                v += __shfl_xor_sync(0xffffffffu, v, 2);
                p[mt][h] = v;
            }
        if (tig == 0) {
#pragma unroll
            for (int mt = 0; mt < 2; mt++)
#pragma unroll
                for (int h = 0; h < 2; h++)
                    spart[Rl + mt * 16 + g + 8 * h][wn] = p[mt][h];
        }
        __syncthreads();
        if (t < 128) {
            float pp = spart[t][0] + spart[t][1] + bstop[0];
            sscale[t] = fmaxf(pp, 0.f) * (float)mask[row0 + t];
        }
        __syncthreads();
    } else {
        __syncthreads();
        if (t < 128) sscale[t] = (float)mask[row0 + t];
        __syncthreads();
    }

    float* OUT = DOC ? g_dvecs : g_qvecs;
#pragma unroll
    for (int mt = 0; mt < 2; mt++)
#pragma unroll
        for (int h = 0; h < 2; h++) {
            int lrow = Rl + mt * 16 + g + 8 * h;
            float s  = sscale[lrow];
            int row  = row0 + lrow;
#pragma unroll
            for (int nt = 0; nt < 8; nt++) {
                int c0 = Cl + nt * 8 + 2 * tig;
                float2 v;
                v.x = (acc[mt][nt][2 * h + 0] + bb[nt][0]) * s;
                v.y = (acc[mt][nt][2 * h + 1] + bb[nt][1]) * s;
                *(float2*)(OUT + (size_t)row * C_ + c0) = v;
            }
        }
}

// ---------------------------------------------------------------------------
// Per-batch scoring via mma.sync tf32. 8 warps = 2 q-halves x 4 k-groups.
// d chunk = 128 k-rows staged per iteration; running masked max in fragments.
// ---------------------------------------------------------------------------
#define QP 132
#define SCORE_SMEM ((32 * QP + 128 * QP + 128) * 4 + 128 * 4)

__global__ void __launch_bounds__(256) score_kernel(
    const float* __restrict__ qh,
    const float* __restrict__ dhid,
    const int*   __restrict__ qmask,
    const int*   __restrict__ dmask,
    const float* __restrict__ merger,
    float*       __restrict__ out)
{
    extern __shared__ float sm[];
    float* qs   = sm;                     // 32 * QP
    float* ds   = sm + 32 * QP;           // 128 * QP
    float* redm = ds + 128 * QP;          // 32 * 4
    int*   dmch = (int*)(redm + 128);     // 128

    __shared__ float s_red[256];
    __shared__ float s_cls;

    const int b    = blockIdx.x;
    const int t    = threadIdx.x;
    const int lane = t & 31;
    const int w    = t >> 5;
    const int g    = lane >> 2, tig = lane & 3;
    const int wq   = w & 1;    // q half (16 rows)
    const int wk   = w >> 1;   // k group (32 of 128-chunk)

    // --- CLS dot over H ---
    {
        const float* qp = qh   + (size_t)b * LQ_ * H_;
        const float* dp = dhid + (size_t)b * LD_ * H_;
        float p = 0.f;
        for (int h = t; h < H_; h += 256) p += qp[h] * dp[h];
        s_red[t] = p;
        __syncthreads();
        for (int s = 128; s > 0; s >>= 1) {
            if (t < s) s_red[t] += s_red[t + s];
            __syncthreads();
        }
        if (t == 0) s_cls = s_red[0];
    }

    // --- Stage q_vecs [32 x 128], tf32-rounded ---
#pragma unroll
    for (int u = 0; u < 4; u++) {
        int i  = t + u * 256;
        int q  = i >> 5;
        int cq = (i & 31) * 4;
        float4 v = *(const float4*)(g_qvecs + (size_t)b * LQ_ * C_ +
                                    (size_t)q * C_ + cq);
        float4 r;
        r.x = tf32_rna(v.x); r.y = tf32_rna(v.y);
        r.z = tf32_rna(v.z); r.w = tf32_rna(v.w);
        *(float4*)&qs[q * QP + cq] = r;
    }

    float mx0 = -1000.f, mx1 = -1000.f;

    for (int ch = 0; ch < 4; ch++) {
        const int k0 = ch * 128;
        __syncthreads();
        // Stage d_vecs chunk [128 x 128], tf32-rounded
#pragma unroll
        for (int u = 0; u < 16; u++) {
            int i  = t + u * 256;
            int k  = i >> 5;
            int cq = (i & 31) * 4;
            float4 v = *(const float4*)(g_dvecs + (size_t)b * LD_ * C_ +
                                        (size_t)(k0 + k) * C_ + cq);
            float4 r;
            r.x = tf32_rna(v.x); r.y = tf32_rna(v.y);
            r.z = tf32_rna(v.z); r.w = tf32_rna(v.w);
            *(float4*)&ds[k * QP + cq] = r;
        }
        if (t < 128) dmch[t] = dmask[b * LD_ + k0 + t];
        __syncthreads();

        float acc[4][4];
#pragma unroll
        for (int nt = 0; nt < 4; nt++)
#pragma unroll
            for (int x = 0; x < 4; x++) acc[nt][x] = 0.f;

#pragma unroll
        for (int cs = 0; cs < 16; cs++) {
            const int c0 = cs * 8;
            uint32_t a0 = __float_as_uint(qs[(wq * 16 + g) * QP + c0 + tig]);
            uint32_t a1 = __float_as_uint(qs[(wq * 16 + g + 8) * QP + c0 + tig]);
            uint32_t a2 = __float_as_uint(qs[(wq * 16 + g) * QP + c0 + tig + 4]);
            uint32_t a3 = __float_as_uint(qs[(wq * 16 + g + 8) * QP + c0 + tig + 4]);
#pragma unroll
            for (int nt = 0; nt < 4; nt++) {
                int n = wk * 32 + nt * 8 + g;
                uint32_t b0 = __float_as_uint(ds[n * QP + c0 + tig]);
                uint32_t b1 = __float_as_uint(ds[n * QP + c0 + tig + 4]);
                mma_tf32(acc[nt], a0, a1, a2, a3, b0, b1);
            }
        }
#pragma unroll
        for (int nt = 0; nt < 4; nt++) {
            int n0 = wk * 32 + nt * 8 + 2 * tig;
            if (dmch[n0]) {
                mx0 = fmaxf(mx0, acc[nt][0]);
                mx1 = fmaxf(mx1, acc[nt][2]);
            }
            if (dmch[n0 + 1]) {
                mx0 = fmaxf(mx0, acc[nt][1]);
                mx1 = fmaxf(mx1, acc[nt][3]);
            }
        }
    }

    // reduce max over the 4-lane quad (cols)
    mx0 = fmaxf(mx0, __shfl_xor_sync(0xffffffffu, mx0, 1));
    mx0 = fmaxf(mx0, __shfl_xor_sync(0xffffffffu, mx0, 2));
    mx1 = fmaxf(mx1, __shfl_xor_sync(0xffffffffu, mx1, 1));
    mx1 = fmaxf(mx1, __shfl_xor_sync(0xffffffffu, mx1, 2));
    __syncthreads();
    if (tig == 0) {
        redm[(wq * 16 + g) * 4 + wk]     = mx0;
        redm[(wq * 16 + g + 8) * 4 + wk] = mx1;
    }
    __syncthreads();

    if (t < 32) {
        float m = fmaxf(fmaxf(redm[t * 4 + 0], redm[t * 4 + 1]),
                        fmaxf(redm[t * 4 + 2], redm[t * 4 + 3]));
        float term = qmask[b * LQ_ + t] ? m : 0.f;
#pragma unroll
        for (int o = 16; o >= 1; o >>= 1)
            term += __shfl_xor_sync(0xffffffffu, term, o);
        if (t == 0) {
            float w_  = 1.f / (1.f + expf(-merger[0]));
            float cls = s_cls * w_;
            float ts  = term * (1.f - w_);
            out[b]          = cls + ts;
            out[B_ + b]     = cls;
            out[2 * B_ + b] = ts;
        }
    }
}

extern "C" void kernel_launch(void* const* d_in, const int* in_sizes, int n_in,
                              void* d_out, int out_size)
{
    const float* query_hidden = (const float*)d_in[0];
    const float* doc_hidden   = (const float*)d_in[1];
    const int*   query_mask   = (const int*)  d_in[2];
    const int*   doc_mask     = (const int*)  d_in[3];
    const float* W_comp       = (const float*)d_in[4];
    const float* b_comp       = (const float*)d_in[5];
    const float* w_stop       = (const float*)d_in[6];
    const float* b_stop       = (const float*)d_in[7];
    const float* score_merger = (const float*)d_in[8];
    float* out = (float*)d_out;

    cudaFuncSetAttribute(gemm_tc<true>,
                         cudaFuncAttributeMaxDynamicSharedMemorySize, GEMM_SMEM);
    cudaFuncSetAttribute(gemm_tc<false>,
                         cudaFuncAttributeMaxDynamicSharedMemorySize, GEMM_SMEM);
    cudaFuncSetAttribute(score_kernel,
                         cudaFuncAttributeMaxDynamicSharedMemorySize, SCORE_SMEM);

    prep_w<<<(H_ * C_ + 255) / 256, 256>>>(W_comp);
    gemm_tc<true><<<(B_ * LD_) / 128, 256, GEMM_SMEM>>>(
        doc_hidden, b_comp, w_stop, b_stop, doc_mask);
    gemm_tc<false><<<(B_ * LQ_) / 128, 256, GEMM_SMEM>>>(
        query_hidden, b_comp, w_stop, b_stop, query_mask);
    score_kernel<<<B_, 256, SCORE_SMEM>>>(
        query_hidden, doc_hidden, query_mask, doc_mask, score_merger, out);
}

// round 5
// speedup vs baseline: 3.8657x; 1.0103x over previous
#include <cuda_runtime.h>
#include <math.h>
#include <stdint.h>

#define B_  128
#define LQ_ 32
#define LD_ 512
#define H_  768
#define C_  128
#define KCH 32
#define NCH (H_ / KCH)   // 24 K-chunks
#define AP  36           // [row][k] pad

// Scratch (__device__ globals: allocation-free rule)
__device__ float g_dvecs[B_ * LD_ * C_];   // 33.5 MB
__device__ float g_qvecs[B_ * LQ_ * C_];   // 2 MB
__device__ float g_Wt[C_ * H_];            // W_comp transposed, tf32-rounded

__device__ __forceinline__ float tf32_rna(float x) {
    uint32_t u;
    asm("cvt.rna.tf32.f32 %0, %1;" : "=r"(u) : "f"(x));
    return __uint_as_float(u);
}
__device__ __forceinline__ uint32_t smem_u32(const void* p) {
    uint32_t a;
    asm("{ .reg .u64 t; cvta.to.shared.u64 t, %1; cvt.u32.u64 %0, t; }"
        : "=r"(a) : "l"(p));
    return a;
}
__device__ __forceinline__ void cp16(void* dst, const void* src) {
    asm volatile("cp.async.cg.shared.global [%0], [%1], 16;"
                 :: "r"(smem_u32(dst)), "l"(src));
}
#define CP_COMMIT() asm volatile("cp.async.commit_group;" ::: "memory")
#define CP_WAIT0()  asm volatile("cp.async.wait_group 0;" ::: "memory")

__device__ __forceinline__ void mma_tf32(float c[4], uint32_t a0, uint32_t a1,
                                         uint32_t a2, uint32_t a3,
                                         uint32_t b0, uint32_t b1) {
    asm volatile(
        "mma.sync.aligned.m16n8k8.row.col.f32.tf32.tf32.f32 "
        "{%0,%1,%2,%3}, {%4,%5,%6,%7}, {%8,%9}, {%0,%1,%2,%3};"
        : "+f"(c[0]), "+f"(c[1]), "+f"(c[2]), "+f"(c[3])
        : "r"(a0), "r"(a1), "r"(a2), "r"(a3), "r"(b0), "r"(b1));
}

// ---------------------------------------------------------------------------
// Prep: transpose W_comp [H,C] -> g_Wt [C,H] (K-major), rounded to tf32
// ---------------------------------------------------------------------------
__global__ void prep_w(const float* __restrict__ W) {
    int idx = blockIdx.x * 256 + threadIdx.x;
    if (idx < H_ * C_) {
        int k = idx / C_, c = idx % C_;
        g_Wt[c * H_ + k] = tf32_rna(W[idx]);
    }
}

// ---------------------------------------------------------------------------
// Pipelined projection GEMM (mma.sync tf32): 128x128 tile/CTA, K=768.
// A: register double-buffer (LDG.128 prefetch, cvt.rna, STS). B: cp.async
// double-buffered smem (pre-rounded g_Wt, L2-resident).
// DOC: fused importance gating + dm mask -> g_dvecs; else qm -> g_qvecs.
// ---------------------------------------------------------------------------
#define GEMM_SMEM (3 * 128 * AP * 4)

template <bool DOC>
__global__ void __launch_bounds__(256, 2) gemm_tc(
    const float* __restrict__ X,
    const float* __restrict__ bcomp,
    const float* __restrict__ wstop,
    const float* __restrict__ bstop,
    const int*   __restrict__ mask)
{
    extern __shared__ float smg[];
    float (*As)[AP]      = (float(*)[AP])smg;                    // [128][AP]
    float (*Bs)[128][AP] = (float(*)[128][AP])(smg + 128 * AP);  // [2][128][AP]

    const int t    = threadIdx.x;
    const int lane = t & 31;
    const int w    = t >> 5;
    const int wm   = w >> 1, wn = w & 1;
    const int g    = lane >> 2, tig = lane & 3;
    const int Rl   = wm * 32, Cl = wn * 64;
    const int row0 = blockIdx.x * 128;

    const int sr  = t >> 3;         // staging row base (0..31)
    const int skq = (t & 7) * 4;    // staging col (floats)

    const float* Xp = X    + (size_t)(row0 + sr) * H_ + skq;
    const float* Wp = g_Wt + (size_t)sr * H_ + skq;

    float4 areg[4];
    float acc[2][8][4];
#pragma unroll
    for (int mt = 0; mt < 2; mt++)
#pragma unroll
        for (int nt = 0; nt < 8; nt++)
#pragma unroll
            for (int x = 0; x < 4; x++) acc[mt][nt][x] = 0.f;

    // ---- prologue: chunk 0 ----
#pragma unroll
    for (int u = 0; u < 4; u++)
        areg[u] = *(const float4*)(Xp + (size_t)(32 * u) * H_);
#pragma unroll
    for (int u = 0; u < 4; u++)
        cp16(&Bs[0][sr + 32 * u][skq], Wp + (size_t)(32 * u) * H_);
    CP_COMMIT();
#pragma unroll
    for (int u = 0; u < 4; u++) {
        float4 v = areg[u];
        float4 r;
        r.x = tf32_rna(v.x); r.y = tf32_rna(v.y);
        r.z = tf32_rna(v.z); r.w = tf32_rna(v.w);
        *(float4*)&As[sr + 32 * u][skq] = r;
    }
    CP_WAIT0();
    __syncthreads();

    for (int ch = 0; ch < NCH; ch++) {
        const bool more = (ch + 1) < NCH;
        const int  ktn  = (ch + 1) * KCH;
        if (more) {
#pragma unroll
            for (int u = 0; u < 4; u++)
                areg[u] = *(const float4*)(Xp + (size_t)(32 * u) * H_ + ktn);
#pragma unroll
            for (int u = 0; u < 4; u++)
                cp16(&Bs[(ch + 1) & 1][sr + 32 * u][skq],
                     Wp + (size_t)(32 * u) * H_ + ktn);
            CP_COMMIT();
        }

        const int p = ch & 1;
#pragma unroll
        for (int ks = 0; ks < 4; ks++) {
            const int k0 = ks * 8;
            uint32_t a[2][4];
#pragma unroll
            for (int mt = 0; mt < 2; mt++) {
                int r = Rl + mt * 16 + g;
                a[mt][0] = __float_as_uint(As[r][k0 + tig]);
                a[mt][1] = __float_as_uint(As[r + 8][k0 + tig]);
                a[mt][2] = __float_as_uint(As[r][k0 + tig + 4]);
                a[mt][3] = __float_as_uint(As[r + 8][k0 + tig + 4]);
            }
#pragma unroll
            for (int nt = 0; nt < 8; nt++) {
                int c = Cl + nt * 8 + g;
                uint32_t b0 = __float_as_uint(Bs[p][c][k0 + tig]);
                uint32_t b1 = __float_as_uint(Bs[p][c][k0 + tig + 4]);
                mma_tf32(acc[0][nt], a[0][0], a[0][1], a[0][2], a[0][3], b0, b1);
                mma_tf32(acc[1][nt], a[1][0], a[1][1], a[1][2], a[1][3], b0, b1);
            }
        }
        __syncthreads();
        if (more) {
#pragma unroll
            for (int u = 0; u < 4; u++) {
                float4 v = areg[u];
                float4 r;
                r.x = tf32_rna(v.x); r.y = tf32_rna(v.y);
                r.z = tf32_rna(v.z); r.w = tf32_rna(v.w);
                *(float4*)&As[sr + 32 * u][skq] = r;
            }
            CP_WAIT0();
        }
        __syncthreads();
    }

    // ---- Epilogue ----
    float bb[8][2];
#pragma unroll
    for (int nt = 0; nt < 8; nt++) {
        int c0 = Cl + nt * 8 + 2 * tig;
        bb[nt][0] = bcomp[c0];
        bb[nt][1] = bcomp[c0 + 1];
    }

    float (*spart)[2] = (float(*)[2])smg;   // 128 x 2 partials
    float* sscale     = smg + 256;          // 128 scales

    if (DOC) {
        float ws[8][2];
#pragma unroll
        for (int nt = 0; nt < 8; nt++) {
            int c0 = Cl + nt * 8 + 2 * tig;
            ws[nt][0] = wstop[c0];
            ws[nt][1] = wstop[c0 + 1];
        }
        float p[2][2] = {{0.f, 0.f}, {0.f, 0.f}};
#pragma unroll
        for (int mt = 0; mt < 2; mt++)
#pragma unroll
            for (int nt = 0; nt < 8; nt++) {
                p[mt][0] += (acc[mt][nt][0] + bb[nt][0]) * ws[nt][0]
                          + (acc[mt][nt][1] + bb[nt][1]) * ws[nt][1];
                p[mt][1] += (acc[mt][nt][2] + bb[nt][0]) * ws[nt][0]
                          + (acc[mt][nt][3] + bb[nt][1]) * ws[nt][1];
            }
#pragma unroll
        for (int mt = 0; mt < 2; mt++)
#pragma unroll
            for (int h = 0; h < 2; h++) {
                float v = p[mt][h];
                v += __shfl_xor_sync(0xffffffffu, v, 1);
                v += __shfl_xor_sync(0xffffffffu, v, 2);
                p[mt][h] = v;
            }
        if (tig == 0) {
#pragma unroll
            for (int mt = 0; mt < 2; mt++)
#pragma unroll
                for (int h = 0; h < 2; h++)
                    spart[Rl + mt * 16 + g + 8 * h][wn] = p[mt][h];
        }
        __syncthreads();
        if (t < 128) {
            float pp = spart[t][0] + spart[t][1] + bstop[0];
            sscale[t] = fmaxf(pp, 0.f) * (float)mask[row0 + t];
        }
        __syncthreads();
    } else {
        __syncthreads();
        if (t < 128) sscale[t] = (float)mask[row0 + t];
        __syncthreads();
    }

    float* OUT = DOC ? g_dvecs : g_qvecs;
#pragma unroll
    for (int mt = 0; mt < 2; mt++)
#pragma unroll
        for (int h = 0; h < 2; h++) {
            int lrow = Rl + mt * 16 + g + 8 * h;
            float s  = sscale[lrow];
            int row  = row0 + lrow;
#pragma unroll
            for (int nt = 0; nt < 8; nt++) {
                int c0 = Cl + nt * 8 + 2 * tig;
                float2 v;
                v.x = (acc[mt][nt][2 * h + 0] + bb[nt][0]) * s;
                v.y = (acc[mt][nt][2 * h + 1] + bb[nt][1]) * s;
                *(float2*)(OUT + (size_t)row * C_ + c0) = v;
            }
        }
}

// ---------------------------------------------------------------------------
// Per-batch scoring via mma.sync tf32. 8 warps = 2 q-halves x 4 k-groups.
// d chunk = 128 k-rows staged per iteration; running masked max in fragments.
// ---------------------------------------------------------------------------
#define QP 132
#define SCORE_SMEM ((32 * QP + 128 * QP + 128) * 4 + 128 * 4)

__global__ void __launch_bounds__(256) score_kernel(
    const float* __restrict__ qh,
    const float* __restrict__ dhid,
    const int*   __restrict__ qmask,
    const int*   __restrict__ dmask,
    const float* __restrict__ merger,
    float*       __restrict__ out)
{
    extern __shared__ float sm[];
    float* qs   = sm;                     // 32 * QP
    float* ds   = sm + 32 * QP;           // 128 * QP
    float* redm = ds + 128 * QP;          // 32 * 4
    int*   dmch = (int*)(redm + 128);     // 128

    __shared__ float s_red[256];
    __shared__ float s_cls;

    const int b    = blockIdx.x;
    const int t    = threadIdx.x;
    const int lane = t & 31;
    const int w    = t >> 5;
    const int g    = lane >> 2, tig = lane & 3;
    const int wq   = w & 1;    // q half (16 rows)
    const int wk   = w >> 1;   // k group (32 of 128-chunk)

    // --- CLS dot over H ---
    {
        const float* qp = qh   + (size_t)b * LQ_ * H_;
        const float* dp = dhid + (size_t)b * LD_ * H_;
        float p = 0.f;
        for (int h = t; h < H_; h += 256) p += qp[h] * dp[h];
        s_red[t] = p;
        __syncthreads();
        for (int s = 128; s > 0; s >>= 1) {
            if (t < s) s_red[t] += s_red[t + s];
            __syncthreads();
        }
        if (t == 0) s_cls = s_red[0];
    }

    // --- Stage q_vecs [32 x 128], tf32-rounded ---
#pragma unroll
    for (int u = 0; u < 4; u++) {
        int i  = t + u * 256;
        int q  = i >> 5;
        int cq = (i & 31) * 4;
        float4 v = *(const float4*)(g_qvecs + (size_t)b * LQ_ * C_ +
                                    (size_t)q * C_ + cq);
        float4 r;
        r.x = tf32_rna(v.x); r.y = tf32_rna(v.y);
        r.z = tf32_rna(v.z); r.w = tf32_rna(v.w);
        *(float4*)&qs[q * QP + cq] = r;
    }

    float mx0 = -1000.f, mx1 = -1000.f;

    for (int ch = 0; ch < 4; ch++) {
        const int k0 = ch * 128;
        __syncthreads();
        // Stage d_vecs chunk [128 x 128], tf32-rounded
#pragma unroll
        for (int u = 0; u < 16; u++) {
            int i  = t + u * 256;
            int k  = i >> 5;
            int cq = (i & 31) * 4;
            float4 v = *(const float4*)(g_dvecs + (size_t)b * LD_ * C_ +
                                        (size_t)(k0 + k) * C_ + cq);
            float4 r;
            r.x = tf32_rna(v.x); r.y = tf32_rna(v.y);
            r.z = tf32_rna(v.z); r.w = tf32_rna(v.w);
            *(float4*)&ds[k * QP + cq] = r;
        }
        if (t < 128) dmch[t] = dmask[b * LD_ + k0 + t];
        __syncthreads();

        float acc[4][4];
#pragma unroll
        for (int nt = 0; nt < 4; nt++)
#pragma unroll
            for (int x = 0; x < 4; x++) acc[nt][x] = 0.f;

#pragma unroll
        for (int cs = 0; cs < 16; cs++) {
            const int c0 = cs * 8;
            uint32_t a0 = __float_as_uint(qs[(wq * 16 + g) * QP + c0 + tig]);
            uint32_t a1 = __float_as_uint(qs[(wq * 16 + g + 8) * QP + c0 + tig]);
            uint32_t a2 = __float_as_uint(qs[(wq * 16 + g) * QP + c0 + tig + 4]);
            uint32_t a3 = __float_as_uint(qs[(wq * 16 + g + 8) * QP + c0 + tig + 4]);
#pragma unroll
            for (int nt = 0; nt < 4; nt++) {
                int n = wk * 32 + nt * 8 + g;
                uint32_t b0 = __float_as_uint(ds[n * QP + c0 + tig]);
                uint32_t b1 = __float_as_uint(ds[n * QP + c0 + tig + 4]);
                mma_tf32(acc[nt], a0, a1, a2, a3, b0, b1);
            }
        }
#pragma unroll
        for (int nt = 0; nt < 4; nt++) {
            int n0 = wk * 32 + nt * 8 + 2 * tig;
            if (dmch[n0]) {
                mx0 = fmaxf(mx0, acc[nt][0]);
                mx1 = fmaxf(mx1, acc[nt][2]);
            }
            if (dmch[n0 + 1]) {
                mx0 = fmaxf(mx0, acc[nt][1]);
                mx1 = fmaxf(mx1, acc[nt][3]);
            }
        }
    }

    // reduce max over the 4-lane quad (cols)
    mx0 = fmaxf(mx0, __shfl_xor_sync(0xffffffffu, mx0, 1));
    mx0 = fmaxf(mx0, __shfl_xor_sync(0xffffffffu, mx0, 2));
    mx1 = fmaxf(mx1, __shfl_xor_sync(0xffffffffu, mx1, 1));
    mx1 = fmaxf(mx1, __shfl_xor_sync(0xffffffffu, mx1, 2));
    __syncthreads();
    if (tig == 0) {
        redm[(wq * 16 + g) * 4 + wk]     = mx0;
        redm[(wq * 16 + g + 8) * 4 + wk] = mx1;
    }
    __syncthreads();

    if (t < 32) {
        float m = fmaxf(fmaxf(redm[t * 4 + 0], redm[t * 4 + 1]),
                        fmaxf(redm[t * 4 + 2], redm[t * 4 + 3]));
        float term = qmask[b * LQ_ + t] ? m : 0.f;
#pragma unroll
        for (int o = 16; o >= 1; o >>= 1)
            term += __shfl_xor_sync(0xffffffffu, term, o);
        if (t == 0) {
            float w_  = 1.f / (1.f + expf(-merger[0]));
            float cls = s_cls * w_;
            float ts  = term * (1.f - w_);
            out[b]          = cls + ts;
            out[B_ + b]     = cls;
            out[2 * B_ + b] = ts;
        }
    }
}

extern "C" void kernel_launch(void* const* d_in, const int* in_sizes, int n_in,
                              void* d_out, int out_size)
{
    const float* query_hidden = (const float*)d_in[0];
    const float* doc_hidden   = (const float*)d_in[1];
    const int*   query_mask   = (const int*)  d_in[2];
    const int*   doc_mask     = (const int*)  d_in[3];
    const float* W_comp       = (const float*)d_in[4];
    const float* b_comp       = (const float*)d_in[5];
    const float* w_stop       = (const float*)d_in[6];
    const float* b_stop       = (const float*)d_in[7];
    const float* score_merger = (const float*)d_in[8];
    float* out = (float*)d_out;

    cudaFuncSetAttribute(gemm_tc<true>,
                         cudaFuncAttributeMaxDynamicSharedMemorySize, GEMM_SMEM);
    cudaFuncSetAttribute(gemm_tc<false>,
                         cudaFuncAttributeMaxDynamicSharedMemorySize, GEMM_SMEM);
    cudaFuncSetAttribute(score_kernel,
                         cudaFuncAttributeMaxDynamicSharedMemorySize, SCORE_SMEM);

    prep_w<<<(H_ * C_ + 255) / 256, 256>>>(W_comp);
    gemm_tc<true><<<(B_ * LD_) / 128, 256, GEMM_SMEM>>>(
        doc_hidden, b_comp, w_stop, b_stop, doc_mask);
    gemm_tc<false><<<(B_ * LQ_) / 128, 256, GEMM_SMEM>>>(
        query_hidden, b_comp, w_stop, b_stop, query_mask);
    score_kernel<<<B_, 256, SCORE_SMEM>>>(
        query_hidden, doc_hidden, query_mask, doc_mask, score_merger, out);
}

// round 6
// speedup vs baseline: 4.0561x; 1.0492x over previous
#include <cuda_runtime.h>
#include <math.h>
#include <stdint.h>

#define B_  128
#define LQ_ 32
#define LD_ 512
#define H_  768
#define C_  128
#define KCH 32
#define NCH (H_ / KCH)   // 24 K-chunks
#define AP  36           // [row][k] pad
#define STG 3            // cp.async pipeline stages

// Scratch (__device__ globals: allocation-free rule)
__device__ float g_dvecs[B_ * LD_ * C_];   // 33.5 MB
__device__ float g_qvecs[B_ * LQ_ * C_];   // 2 MB
__device__ float g_Wt[C_ * H_];            // W_comp transposed, tf32-rounded
__device__ float g_pmax[B_ * 4 * LQ_];     // split-K partial maxima

__device__ __forceinline__ float tf32_rna(float x) {
    uint32_t u;
    asm("cvt.rna.tf32.f32 %0, %1;" : "=r"(u) : "f"(x));
    return __uint_as_float(u);
}
__device__ __forceinline__ uint32_t smem_u32(const void* p) {
    uint32_t a;
    asm("{ .reg .u64 t; cvta.to.shared.u64 t, %1; cvt.u32.u64 %0, t; }"
        : "=r"(a) : "l"(p));
    return a;
}
__device__ __forceinline__ void cp16(void* dst, const void* src) {
    asm volatile("cp.async.cg.shared.global [%0], [%1], 16;"
                 :: "r"(smem_u32(dst)), "l"(src));
}
#define CP_COMMIT() asm volatile("cp.async.commit_group;" ::: "memory")
#define CP_WAIT1()  asm volatile("cp.async.wait_group 1;" ::: "memory")

__device__ __forceinline__ void mma_tf32(float c[4], uint32_t a0, uint32_t a1,
                                         uint32_t a2, uint32_t a3,
                                         uint32_t b0, uint32_t b1) {
    asm volatile(
        "mma.sync.aligned.m16n8k8.row.col.f32.tf32.tf32.f32 "
        "{%0,%1,%2,%3}, {%4,%5,%6,%7}, {%8,%9}, {%0,%1,%2,%3};"
        : "+f"(c[0]), "+f"(c[1]), "+f"(c[2]), "+f"(c[3])
        : "r"(a0), "r"(a1), "r"(a2), "r"(a3), "r"(b0), "r"(b1));
}

// ---------------------------------------------------------------------------
// Prep: transpose W_comp [H,C] -> g_Wt [C,H] (K-major), rounded to tf32
// ---------------------------------------------------------------------------
__global__ void prep_w(const float* __restrict__ W) {
    int idx = blockIdx.x * 256 + threadIdx.x;
    if (idx < H_ * C_) {
        int k = idx / C_, c = idx % C_;
        g_Wt[c * H_ + k] = tf32_rna(W[idx]);
    }
}

// ---------------------------------------------------------------------------
// 3-stage cp.async pipelined projection GEMM (mma.sync tf32).
// 128x128 tile/CTA, K=768. A raw fp32 staged, cvt.rna at fragment load.
// B pre-rounded (g_Wt). One __syncthreads per chunk.
// DOC: fused importance gating + dm mask -> g_dvecs; else qm -> g_qvecs.
// ---------------------------------------------------------------------------
#define GEMM_SMEM (STG * 2 * 128 * AP * 4)

template <bool DOC>
__global__ void __launch_bounds__(256, 2) gemm_tc(
    const float* __restrict__ X,
    const float* __restrict__ bcomp,
    const float* __restrict__ wstop,
    const float* __restrict__ bstop,
    const int*   __restrict__ mask)
{
    extern __shared__ float smg[];

    const int t    = threadIdx.x;
    const int lane = t & 31;
    const int w    = t >> 5;
    const int wm   = w >> 1, wn = w & 1;
    const int g    = lane >> 2, tig = lane & 3;
    const int Rl   = wm * 32, Cl = wn * 64;
    const int row0 = blockIdx.x * 128;

    const int sr  = t >> 3;         // staging row base (0..31)
    const int skq = (t & 7) * 4;    // staging col (floats)

    const float* Xp = X    + (size_t)(row0 + sr) * H_ + skq;
    const float* Wp = g_Wt + (size_t)sr * H_ + skq;

    float acc[2][8][4];
#pragma unroll
    for (int mt = 0; mt < 2; mt++)
#pragma unroll
        for (int nt = 0; nt < 8; nt++)
#pragma unroll
            for (int x = 0; x < 4; x++) acc[mt][nt][x] = 0.f;

    // ---- prologue: stage chunks 0,1 ----
#pragma unroll
    for (int s = 0; s < 2; s++) {
        float* As = smg + s * (2 * 128 * AP);
        float* Bs = As + 128 * AP;
        const int kt = s * KCH;
#pragma unroll
        for (int u = 0; u < 4; u++)
            cp16(&As[(sr + 32 * u) * AP + skq], Xp + (size_t)(32 * u) * H_ + kt);
#pragma unroll
        for (int u = 0; u < 4; u++)
            cp16(&Bs[(sr + 32 * u) * AP + skq], Wp + (size_t)(32 * u) * H_ + kt);
        CP_COMMIT();
    }

    int snext = 2;   // stage index to fill next
    for (int ch = 0; ch < NCH; ch++) {
        CP_WAIT1();          // chunk ch resident
        __syncthreads();

        if (ch + 2 < NCH) {
            float* As = smg + snext * (2 * 128 * AP);
            float* Bs = As + 128 * AP;
            const int kt = (ch + 2) * KCH;
#pragma unroll
            for (int u = 0; u < 4; u++)
                cp16(&As[(sr + 32 * u) * AP + skq],
                     Xp + (size_t)(32 * u) * H_ + kt);
#pragma unroll
            for (int u = 0; u < 4; u++)
                cp16(&Bs[(sr + 32 * u) * AP + skq],
                     Wp + (size_t)(32 * u) * H_ + kt);
            CP_COMMIT();
            snext = (snext + 1 == STG) ? 0 : snext + 1;
        } else {
            CP_COMMIT();     // keep group count cadence for wait_group 1
        }

        const int sc = ch % STG;
        const float* As = smg + sc * (2 * 128 * AP);
        const float* Bs = As + 128 * AP;

#pragma unroll
        for (int ks = 0; ks < 4; ks++) {
            const int k0 = ks * 8;
            uint32_t a[2][4];
#pragma unroll
            for (int mt = 0; mt < 2; mt++) {
                int r = Rl + mt * 16 + g;
                a[mt][0] = __float_as_uint(tf32_rna(As[r * AP + k0 + tig]));
                a[mt][1] = __float_as_uint(tf32_rna(As[(r + 8) * AP + k0 + tig]));
                a[mt][2] = __float_as_uint(tf32_rna(As[r * AP + k0 + tig + 4]));
                a[mt][3] = __float_as_uint(tf32_rna(As[(r + 8) * AP + k0 + tig + 4]));
            }
#pragma unroll
            for (int nt = 0; nt < 8; nt++) {
                int c = Cl + nt * 8 + g;
                uint32_t b0 = __float_as_uint(Bs[c * AP + k0 + tig]);
                uint32_t b1 = __float_as_uint(Bs[c * AP + k0 + tig + 4]);
                mma_tf32(acc[0][nt], a[0][0], a[0][1], a[0][2], a[0][3], b0, b1);
                mma_tf32(acc[1][nt], a[1][0], a[1][1], a[1][2], a[1][3], b0, b1);
            }
        }
    }
    __syncthreads();

    // ---- Epilogue ----
    float bb[8][2];
#pragma unroll
    for (int nt = 0; nt < 8; nt++) {
        int c0 = Cl + nt * 8 + 2 * tig;
        bb[nt][0] = bcomp[c0];
        bb[nt][1] = bcomp[c0 + 1];
    }

    float (*spart)[2] = (float(*)[2])smg;   // 128 x 2 partials
    float* sscale     = smg + 256;          // 128 scales

    if (DOC) {
        float ws[8][2];
#pragma unroll
        for (int nt = 0; nt < 8; nt++) {
            int c0 = Cl + nt * 8 + 2 * tig;
            ws[nt][0] = wstop[c0];
            ws[nt][1] = wstop[c0 + 1];
        }
        float p[2][2] = {{0.f, 0.f}, {0.f, 0.f}};
#pragma unroll
        for (int mt = 0; mt < 2; mt++)
#pragma unroll
            for (int nt = 0; nt < 8; nt++) {
                p[mt][0] += (acc[mt][nt][0] + bb[nt][0]) * ws[nt][0]
                          + (acc[mt][nt][1] + bb[nt][1]) * ws[nt][1];
                p[mt][1] += (acc[mt][nt][2] + bb[nt][0]) * ws[nt][0]
                          + (acc[mt][nt][3] + bb[nt][1]) * ws[nt][1];
            }
#pragma unroll
        for (int mt = 0; mt < 2; mt++)
#pragma unroll
            for (int h = 0; h < 2; h++) {
                float v = p[mt][h];
                v += __shfl_xor_sync(0xffffffffu, v, 1);
                v += __shfl_xor_sync(0xffffffffu, v, 2);
                p[mt][h] = v;
            }
        if (tig == 0) {
#pragma unroll
            for (int mt = 0; mt < 2; mt++)
#pragma unroll
                for (int h = 0; h < 2; h++)
                    spart[Rl + mt * 16 + g + 8 * h][wn] = p[mt][h];
        }
        __syncthreads();
        if (t < 128) {
            float pp = spart[t][0] + spart[t][1] + bstop[0];
            sscale[t] = fmaxf(pp, 0.f) * (float)mask[row0 + t];
        }
        __syncthreads();
    } else {
        if (t < 128) sscale[t] = (float)mask[row0 + t];
        __syncthreads();
    }

    float* OUT = DOC ? g_dvecs : g_qvecs;
#pragma unroll
    for (int mt = 0; mt < 2; mt++)
#pragma unroll
        for (int h = 0; h < 2; h++) {
            int lrow = Rl + mt * 16 + g + 8 * h;
            float s  = sscale[lrow];
            int row  = row0 + lrow;
#pragma unroll
            for (int nt = 0; nt < 8; nt++) {
                int c0 = Cl + nt * 8 + 2 * tig;
                float2 v;
                v.x = (acc[mt][nt][2 * h + 0] + bb[nt][0]) * s;
                v.y = (acc[mt][nt][2 * h + 1] + bb[nt][1]) * s;
                *(float2*)(OUT + (size_t)row * C_ + c0) = v;
            }
        }
}

// ---------------------------------------------------------------------------
// Split-K scoring stage 1: CTA (b, ci) computes masked max of
// q_vecs[b] @ d_vecs[b, ci*128 : ci*128+128]^T  ->  g_pmax[b][ci][32]
// ---------------------------------------------------------------------------
#define QP 132
#define SP_SMEM ((32 * QP + 128 * QP + 128) * 4 + 128 * 4)

__global__ void __launch_bounds__(256) score_partial(
    const int* __restrict__ dmask)
{
    extern __shared__ float sm[];
    float* qs   = sm;                     // 32 * QP
    float* ds   = sm + 32 * QP;           // 128 * QP
    float* redm = ds + 128 * QP;          // 32 * 4
    int*   dmch = (int*)(redm + 128);     // 128

    const int b    = blockIdx.x >> 2;
    const int ci   = blockIdx.x & 3;
    const int k0   = ci * 128;
    const int t    = threadIdx.x;
    const int lane = t & 31;
    const int w    = t >> 5;
    const int g    = lane >> 2, tig = lane & 3;
    const int wq   = w & 1;    // q half (16 rows)
    const int wk   = w >> 1;   // k group (32 rows)

    // Stage q_vecs [32 x 128] (tf32) and d chunk [128 x 128] (tf32)
#pragma unroll
    for (int u = 0; u < 4; u++) {
        int i  = t + u * 256;
        int q  = i >> 5;
        int cq = (i & 31) * 4;
        float4 v = *(const float4*)(g_qvecs + (size_t)b * LQ_ * C_ +
                                    (size_t)q * C_ + cq);
        float4 r;
        r.x = tf32_rna(v.x); r.y = tf32_rna(v.y);
        r.z = tf32_rna(v.z); r.w = tf32_rna(v.w);
        *(float4*)&qs[q * QP + cq] = r;
    }
#pragma unroll
    for (int u = 0; u < 16; u++) {
        int i  = t + u * 256;
        int k  = i >> 5;
        int cq = (i & 31) * 4;
        float4 v = *(const float4*)(g_dvecs + (size_t)b * LD_ * C_ +
                                    (size_t)(k0 + k) * C_ + cq);
        float4 r;
        r.x = tf32_rna(v.x); r.y = tf32_rna(v.y);
        r.z = tf32_rna(v.z); r.w = tf32_rna(v.w);
        *(float4*)&ds[k * QP + cq] = r;
    }
    if (t < 128) dmch[t] = dmask[b * LD_ + k0 + t];
    __syncthreads();

    float acc[4][4];
#pragma unroll
    for (int nt = 0; nt < 4; nt++)
#pragma unroll
        for (int x = 0; x < 4; x++) acc[nt][x] = 0.f;

#pragma unroll
    for (int cs = 0; cs < 16; cs++) {
        const int c0 = cs * 8;
        uint32_t a0 = __float_as_uint(qs[(wq * 16 + g) * QP + c0 + tig]);
        uint32_t a1 = __float_as_uint(qs[(wq * 16 + g + 8) * QP + c0 + tig]);
        uint32_t a2 = __float_as_uint(qs[(wq * 16 + g) * QP + c0 + tig + 4]);
        uint32_t a3 = __float_as_uint(qs[(wq * 16 + g + 8) * QP + c0 + tig + 4]);
#pragma unroll
        for (int nt = 0; nt < 4; nt++) {
            int n = wk * 32 + nt * 8 + g;
            uint32_t b0 = __float_as_uint(ds[n * QP + c0 + tig]);
            uint32_t b1 = __float_as_uint(ds[n * QP + c0 + tig + 4]);
            mma_tf32(acc[nt], a0, a1, a2, a3, b0, b1);
        }
    }

    float mx0 = -1000.f, mx1 = -1000.f;
#pragma unroll
    for (int nt = 0; nt < 4; nt++) {
        int n0 = wk * 32 + nt * 8 + 2 * tig;
        if (dmch[n0]) {
            mx0 = fmaxf(mx0, acc[nt][0]);
            mx1 = fmaxf(mx1, acc[nt][2]);
        }
        if (dmch[n0 + 1]) {
            mx0 = fmaxf(mx0, acc[nt][1]);
            mx1 = fmaxf(mx1, acc[nt][3]);
        }
    }
    mx0 = fmaxf(mx0, __shfl_xor_sync(0xffffffffu, mx0, 1));
    mx0 = fmaxf(mx0, __shfl_xor_sync(0xffffffffu, mx0, 2));
    mx1 = fmaxf(mx1, __shfl_xor_sync(0xffffffffu, mx1, 1));
    mx1 = fmaxf(mx1, __shfl_xor_sync(0xffffffffu, mx1, 2));
    __syncthreads();
    if (tig == 0) {
        redm[(wq * 16 + g) * 4 + wk]     = mx0;
        redm[(wq * 16 + g + 8) * 4 + wk] = mx1;
    }
    __syncthreads();

    if (t < 32) {
        float m = fmaxf(fmaxf(redm[t * 4 + 0], redm[t * 4 + 1]),
                        fmaxf(redm[t * 4 + 2], redm[t * 4 + 3]));
        g_pmax[(b * 4 + ci) * LQ_ + t] = m;
    }
}

// ---------------------------------------------------------------------------
// Split-K scoring stage 2: CLS dot + merge of 4 partial maxima per batch
// ---------------------------------------------------------------------------
__global__ void __launch_bounds__(256) score_final(
    const float* __restrict__ qh,
    const float* __restrict__ dhid,
    const int*   __restrict__ qmask,
    const float* __restrict__ merger,
    float*       __restrict__ out)
{
    __shared__ float s_red[256];

    const int b = blockIdx.x;
    const int t = threadIdx.x;

    const float* qp = qh   + (size_t)b * LQ_ * H_;
    const float* dp = dhid + (size_t)b * LD_ * H_;
    float p = 0.f;
    for (int h = t; h < H_; h += 256) p += qp[h] * dp[h];
    s_red[t] = p;
    __syncthreads();
    for (int s = 128; s > 0; s >>= 1) {
        if (t < s) s_red[t] += s_red[t + s];
        __syncthreads();
    }

    if (t < 32) {
        float m = fmaxf(
            fmaxf(g_pmax[(b * 4 + 0) * LQ_ + t], g_pmax[(b * 4 + 1) * LQ_ + t]),
            fmaxf(g_pmax[(b * 4 + 2) * LQ_ + t], g_pmax[(b * 4 + 3) * LQ_ + t]));
        float term = qmask[b * LQ_ + t] ? m : 0.f;
#pragma unroll
        for (int o = 16; o >= 1; o >>= 1)
            term += __shfl_xor_sync(0xffffffffu, term, o);
        if (t == 0) {
            float w_  = 1.f / (1.f + expf(-merger[0]));
            float cls = s_red[0] * w_;
            float ts  = term * (1.f - w_);
            out[b]          = cls + ts;
            out[B_ + b]     = cls;
            out[2 * B_ + b] = ts;
        }
    }
}

extern "C" void kernel_launch(void* const* d_in, const int* in_sizes, int n_in,
                              void* d_out, int out_size)
{
    const float* query_hidden = (const float*)d_in[0];
    const float* doc_hidden   = (const float*)d_in[1];
    const int*   query_mask   = (const int*)  d_in[2];
    const int*   doc_mask     = (const int*)  d_in[3];
    const float* W_comp       = (const float*)d_in[4];
    const float* b_comp       = (const float*)d_in[5];
    const float* w_stop       = (const float*)d_in[6];
    const float* b_stop       = (const float*)d_in[7];
    const float* score_merger = (const float*)d_in[8];
    float* out = (float*)d_out;

    cudaFuncSetAttribute(gemm_tc<true>,
                         cudaFuncAttributeMaxDynamicSharedMemorySize, GEMM_SMEM);
    cudaFuncSetAttribute(gemm_tc<false>,
                         cudaFuncAttributeMaxDynamicSharedMemorySize, GEMM_SMEM);
    cudaFuncSetAttribute(score_partial,
                         cudaFuncAttributeMaxDynamicSharedMemorySize, SP_SMEM);

    prep_w<<<(H_ * C_ + 255) / 256, 256>>>(W_comp);
    gemm_tc<false><<<(B_ * LQ_) / 128, 256, GEMM_SMEM>>>(
        query_hidden, b_comp, w_stop, b_stop, query_mask);
    gemm_tc<true><<<(B_ * LD_) / 128, 256, GEMM_SMEM>>>(
        doc_hidden, b_comp, w_stop, b_stop, doc_mask);
    score_partial<<<B_ * 4, 256, SP_SMEM>>>(doc_mask);
    score_final<<<B_, 256>>>(
        query_hidden, doc_hidden, query_mask, score_merger, out);
}

// round 9
// speedup vs baseline: 4.9276x; 1.2149x over previous
#include <cuda_runtime.h>
#include <cuda_fp16.h>
#include <math.h>
#include <stdint.h>

#define B_  128
#define LQ_ 32
#define LD_ 512
#define H_  768
#define C_  128
#define KCH 32
#define NCH (H_ / KCH)   // 24 K-chunks
#define AP  36           // A [row][k] pad (fp32)
#define BPh 40           // B [col][k] pad (fp16)
#define STG 3            // cp.async pipeline stages

// Scratch (__device__ globals: allocation-free rule)
__device__ __half g_dvecs[B_ * LD_ * C_];   // 16.7 MB
__device__ __half g_qvecs[B_ * LQ_ * C_];   // 1 MB
__device__ __half g_Wth[C_ * H_];           // W_comp transposed, fp16
__device__ float  g_pmax[B_ * 4 * LQ_];     // split-K partial maxima

__device__ __forceinline__ uint32_t smem_u32(const void* p) {
    uint32_t a;
    asm("{ .reg .u64 t; cvta.to.shared.u64 t, %1; cvt.u32.u64 %0, t; }"
        : "=r"(a) : "l"(p));
    return a;
}
__device__ __forceinline__ void cp16(void* dst, const void* src) {
    asm volatile("cp.async.cg.shared.global [%0], [%1], 16;"
                 :: "r"(smem_u32(dst)), "l"(src));
}
#define CP_COMMIT() asm volatile("cp.async.commit_group;" ::: "memory")
#define CP_WAIT1()  asm volatile("cp.async.wait_group 1;" ::: "memory")

__device__ __forceinline__ uint32_t h2u(float x, float y) {
    __half2 h = __floats2half2_rn(x, y);
    return *(uint32_t*)&h;
}

__device__ __forceinline__ void mma_f16(float c[4], uint32_t a0, uint32_t a1,
                                        uint32_t a2, uint32_t a3,
                                        uint32_t b0, uint32_t b1) {
    asm volatile(
        "mma.sync.aligned.m16n8k16.row.col.f32.f16.f16.f32 "
        "{%0,%1,%2,%3}, {%4,%5,%6,%7}, {%8,%9}, {%0,%1,%2,%3};"
        : "+f"(c[0]), "+f"(c[1]), "+f"(c[2]), "+f"(c[3])
        : "r"(a0), "r"(a1), "r"(a2), "r"(a3), "r"(b0), "r"(b1));
}

// ---------------------------------------------------------------------------
// Prep: transpose W_comp [H,C] -> g_Wth [C,H] (K-major), fp16
// ---------------------------------------------------------------------------
__global__ void prep_w(const float* __restrict__ W) {
    int idx = blockIdx.x * 256 + threadIdx.x;
    if (idx < H_ * C_) {
        int k = idx / C_, c = idx % C_;
        g_Wth[c * H_ + k] = __float2half_rn(W[idx]);
    }
}

// ---------------------------------------------------------------------------
// 3-stage cp.async pipelined projection GEMM (mma.sync fp16, fp32 accum).
// 128x128 tile/CTA, K=768. A fp32 staged (cvt at fragment load), B fp16.
// DOC: fused importance gating + dm mask -> g_dvecs; else qm -> g_qvecs.
// ---------------------------------------------------------------------------
#define A_BYTES (128 * AP * 4)
#define B_BYTES (128 * BPh * 2)
#define STAGE_BYTES (A_BYTES + B_BYTES)
#define GEMM_SMEM (STG * STAGE_BYTES)

template <bool DOC>
__global__ void __launch_bounds__(256, 2) gemm_tc(
    const float* __restrict__ X,
    const float* __restrict__ bcomp,
    const float* __restrict__ wstop,
    const float* __restrict__ bstop,
    const int*   __restrict__ mask)
{
    extern __shared__ char smg[];

    const int t    = threadIdx.x;
    const int lane = t & 31;
    const int w    = t >> 5;
    const int wm   = w >> 1, wn = w & 1;
    const int g    = lane >> 2, tig = lane & 3;
    const int Rl   = wm * 32, Cl = wn * 64;
    const int row0 = blockIdx.x * 128;

    // A staging: row = t>>3 (+32u), col quad = (t&7)*4 floats
    const int sar = t >> 3;
    const int sak = (t & 7) * 4;
    const float* Xp = X + (size_t)(row0 + sar) * H_ + sak;

    float acc[2][8][4];
#pragma unroll
    for (int mt = 0; mt < 2; mt++)
#pragma unroll
        for (int nt = 0; nt < 8; nt++)
#pragma unroll
            for (int x = 0; x < 4; x++) acc[mt][nt][x] = 0.f;

    // ---- prologue: stage chunks 0,1 ----
#pragma unroll
    for (int s = 0; s < 2; s++) {
        float*  As = (float*)(smg + s * STAGE_BYTES);
        __half* Bs = (__half*)(smg + s * STAGE_BYTES + A_BYTES);
        const int kt = s * KCH;
#pragma unroll
        for (int u = 0; u < 4; u++)
            cp16(&As[(sar + 32 * u) * AP + sak], Xp + (size_t)(32 * u) * H_ + kt);
#pragma unroll
        for (int u = 0; u < 2; u++) {
            int i  = t + u * 256;
            int cb = i >> 2;
            int k8 = (i & 3) * 8;
            cp16(&Bs[cb * BPh + k8], g_Wth + (size_t)cb * H_ + kt + k8);
        }
        CP_COMMIT();
    }

    int snext = 2;
    for (int ch = 0; ch < NCH; ch++) {
        CP_WAIT1();
        __syncthreads();

        if (ch + 2 < NCH) {
            float*  As = (float*)(smg + snext * STAGE_BYTES);
            __half* Bs = (__half*)(smg + snext * STAGE_BYTES + A_BYTES);
            const int kt = (ch + 2) * KCH;
#pragma unroll
            for (int u = 0; u < 4; u++)
                cp16(&As[(sar + 32 * u) * AP + sak],
                     Xp + (size_t)(32 * u) * H_ + kt);
#pragma unroll
            for (int u = 0; u < 2; u++) {
                int i  = t + u * 256;
                int cb = i >> 2;
                int k8 = (i & 3) * 8;
                cp16(&Bs[cb * BPh + k8], g_Wth + (size_t)cb * H_ + kt + k8);
            }
            CP_COMMIT();
            snext = (snext + 1 == STG) ? 0 : snext + 1;
        } else {
            CP_COMMIT();
        }

        const int sc = ch % STG;
        const float*  As = (const float*)(smg + sc * STAGE_BYTES);
        const __half* Bs = (const __half*)(smg + sc * STAGE_BYTES + A_BYTES);

#pragma unroll
        for (int ks = 0; ks < 2; ks++) {
            const int k0 = ks * 16;
            uint32_t a[2][4];
#pragma unroll
            for (int mt = 0; mt < 2; mt++) {
                int r = Rl + mt * 16 + g;
                float2 f0 = *(const float2*)&As[r * AP + k0 + 2 * tig];
                float2 f1 = *(const float2*)&As[(r + 8) * AP + k0 + 2 * tig];
                float2 f2 = *(const float2*)&As[r * AP + k0 + 8 + 2 * tig];
                float2 f3 = *(const float2*)&As[(r + 8) * AP + k0 + 8 + 2 * tig];
                a[mt][0] = h2u(f0.x, f0.y);
                a[mt][1] = h2u(f1.x, f1.y);
                a[mt][2] = h2u(f2.x, f2.y);
                a[mt][3] = h2u(f3.x, f3.y);
            }
#pragma unroll
            for (int nt = 0; nt < 8; nt++) {
                int c = Cl + nt * 8 + g;
                uint32_t b0 = *(const uint32_t*)&Bs[c * BPh + k0 + 2 * tig];
                uint32_t b1 = *(const uint32_t*)&Bs[c * BPh + k0 + 8 + 2 * tig];
                mma_f16(acc[0][nt], a[0][0], a[0][1], a[0][2], a[0][3], b0, b1);
                mma_f16(acc[1][nt], a[1][0], a[1][1], a[1][2], a[1][3], b0, b1);
            }
        }
    }
    __syncthreads();

    // ---- Epilogue ----
    float bb[8][2];
#pragma unroll
    for (int nt = 0; nt < 8; nt++) {
        int c0 = Cl + nt * 8 + 2 * tig;
        bb[nt][0] = bcomp[c0];
        bb[nt][1] = bcomp[c0 + 1];
    }

    float (*spart)[2] = (float(*)[2])smg;        // 128 x 2 partials
    float* sscale     = (float*)smg + 256;       // 128 scales

    if (DOC) {
        float ws[8][2];
#pragma unroll
        for (int nt = 0; nt < 8; nt++) {
            int c0 = Cl + nt * 8 + 2 * tig;
            ws[nt][0] = wstop[c0];
            ws[nt][1] = wstop[c0 + 1];
        }
        float p[2][2] = {{0.f, 0.f}, {0.f, 0.f}};
#pragma unroll
        for (int mt = 0; mt < 2; mt++)
#pragma unroll
            for (int nt = 0; nt < 8; nt++) {
                p[mt][0] += (acc[mt][nt][0] + bb[nt][0]) * ws[nt][0]
                          + (acc[mt][nt][1] + bb[nt][1]) * ws[nt][1];
                p[mt][1] += (acc[mt][nt][2] + bb[nt][0]) * ws[nt][0]
                          + (acc[mt][nt][3] + bb[nt][1]) * ws[nt][1];
            }
#pragma unroll
        for (int mt = 0; mt < 2; mt++)
#pragma unroll
            for (int h = 0; h < 2; h++) {
                float v = p[mt][h];
                v += __shfl_xor_sync(0xffffffffu, v, 1);
                v += __shfl_xor_sync(0xffffffffu, v, 2);
                p[mt][h] = v;
            }
        if (tig == 0) {
#pragma unroll
            for (int mt = 0; mt < 2; mt++)
#pragma unroll
                for (int h = 0; h < 2; h++)
                    spart[Rl + mt * 16 + g + 8 * h][wn] = p[mt][h];
        }
        __syncthreads();
        if (t < 128) {
            float pp = spart[t][0] + spart[t][1] + bstop[0];
            sscale[t] = fmaxf(pp, 0.f) * (float)mask[row0 + t];
        }
        __syncthreads();
    } else {
        if (t < 128) sscale[t] = (float)mask[row0 + t];
        __syncthreads();
    }

    __half* OUT = DOC ? g_dvecs : g_qvecs;
#pragma unroll
    for (int mt = 0; mt < 2; mt++)
#pragma unroll
        for (int h = 0; h < 2; h++) {
            int lrow = Rl + mt * 16 + g + 8 * h;
            float s  = sscale[lrow];
            int row  = row0 + lrow;
#pragma unroll
            for (int nt = 0; nt < 8; nt++) {
                int c0 = Cl + nt * 8 + 2 * tig;
                uint32_t hv = h2u((acc[mt][nt][2 * h + 0] + bb[nt][0]) * s,
                                  (acc[mt][nt][2 * h + 1] + bb[nt][1]) * s);
                *(uint32_t*)(OUT + (size_t)row * C_ + c0) = hv;
            }
        }
}

// ---------------------------------------------------------------------------
// Split-K scoring stage 1 (fp16 mma): CTA (b, ci) computes masked max of
// q_vecs[b] @ d_vecs[b, ci*128 : +128]^T  ->  g_pmax[b][ci][32]
// ---------------------------------------------------------------------------
#define QPh 136
#define SP_SMEM ((32 * QPh + 128 * QPh) * 2 + 128 * 4 + 128 * 4)

__global__ void __launch_bounds__(256) score_partial(
    const int* __restrict__ dmask)
{
    extern __shared__ char smc[];
    __half* qs   = (__half*)smc;                        // 32 * QPh
    __half* ds   = qs + 32 * QPh;                       // 128 * QPh
    float*  redm = (float*)(ds + 128 * QPh);            // 32 * 4
    int*    dmch = (int*)(redm + 128);                  // 128

    const int b    = blockIdx.x >> 2;
    const int ci   = blockIdx.x & 3;
    const int k0g  = ci * 128;
    const int t    = threadIdx.x;
    const int lane = t & 31;
    const int w    = t >> 5;
    const int g    = lane >> 2, tig = lane & 3;
    const int wq   = w & 1;    // q half (16 rows)
    const int wk   = w >> 1;   // k group (32 rows)

    // Stage q_vecs [32 x 128] fp16 (512 x 8 halfs = 4096)
#pragma unroll
    for (int u = 0; u < 2; u++) {
        int i  = t + u * 256;
        int q  = i >> 4;
        int c8 = (i & 15) * 8;
        *(uint4*)&qs[q * QPh + c8] = *(const uint4*)(
            g_qvecs + (size_t)b * LQ_ * C_ + (size_t)q * C_ + c8);
    }
    // Stage d chunk [128 x 128] fp16 (2048 x 8 halfs = 16384)
#pragma unroll
    for (int u = 0; u < 8; u++) {
        int i  = t + u * 256;
        int k  = i >> 4;
        int c8 = (i & 15) * 8;
        *(uint4*)&ds[k * QPh + c8] = *(const uint4*)(
            g_dvecs + (size_t)b * LD_ * C_ + (size_t)(k0g + k) * C_ + c8);
    }
    if (t < 128) dmch[t] = dmask[b * LD_ + k0g + t];
    __syncthreads();

    float acc[4][4];
#pragma unroll
    for (int nt = 0; nt < 4; nt++)
#pragma unroll
        for (int x = 0; x < 4; x++) acc[nt][x] = 0.f;

#pragma unroll
    for (int cs = 0; cs < 8; cs++) {
        const int c0 = cs * 16;
        uint32_t a0 = *(const uint32_t*)&qs[(wq * 16 + g) * QPh + c0 + 2 * tig];
        uint32_t a1 = *(const uint32_t*)&qs[(wq * 16 + g + 8) * QPh + c0 + 2 * tig];
        uint32_t a2 = *(const uint32_t*)&qs[(wq * 16 + g) * QPh + c0 + 8 + 2 * tig];
        uint32_t a3 = *(const uint32_t*)&qs[(wq * 16 + g + 8) * QPh + c0 + 8 + 2 * tig];
#pragma unroll
        for (int nt = 0; nt < 4; nt++) {
            int n = wk * 32 + nt * 8 + g;
            uint32_t b0 = *(const uint32_t*)&ds[n * QPh + c0 + 2 * tig];
            uint32_t b1 = *(const uint32_t*)&ds[n * QPh + c0 + 8 + 2 * tig];
            mma_f16(acc[nt], a0, a1, a2, a3, b0, b1);
        }
    }

    float mx0 = -1000.f, mx1 = -1000.f;
#pragma unroll
    for (int nt = 0; nt < 4; nt++) {
        int n0 = wk * 32 + nt * 8 + 2 * tig;
        if (dmch[n0]) {
            mx0 = fmaxf(mx0, acc[nt][0]);
            mx1 = fmaxf(mx1, acc[nt][2]);
        }
        if (dmch[n0 + 1]) {
            mx0 = fmaxf(mx0, acc[nt][1]);
            mx1 = fmaxf(mx1, acc[nt][3]);
        }
    }
    mx0 = fmaxf(mx0, __shfl_xor_sync(0xffffffffu, mx0, 1));
    mx0 = fmaxf(mx0, __shfl_xor_sync(0xffffffffu, mx0, 2));
    mx1 = fmaxf(mx1, __shfl_xor_sync(0xffffffffu, mx1, 1));
    mx1 = fmaxf(mx1, __shfl_xor_sync(0xffffffffu, mx1, 2));
    __syncthreads();
    if (tig == 0) {
        redm[(wq * 16 + g) * 4 + wk]     = mx0;
        redm[(wq * 16 + g + 8) * 4 + wk] = mx1;
    }
    __syncthreads();

    if (t < 32) {
        float m = fmaxf(fmaxf(redm[t * 4 + 0], redm[t * 4 + 1]),
                        fmaxf(redm[t * 4 + 2], redm[t * 4 + 3]));
        g_pmax[(b * 4 + ci) * LQ_ + t] = m;
    }
}

// ---------------------------------------------------------------------------
// Split-K scoring stage 2: CLS dot + merge of 4 partial maxima per batch
// ---------------------------------------------------------------------------
__global__ void __launch_bounds__(256) score_final(
    const float* __restrict__ qh,
    const float* __restrict__ dhid,
    const int*   __restrict__ qmask,
    const float* __restrict__ merger,
    float*       __restrict__ out)
{
    __shared__ float s_red[256];

    const int b = blockIdx.x;
    const int t = threadIdx.x;

    const float* qp = qh   + (size_t)b * LQ_ * H_;
    const float* dp = dhid + (size_t)b * LD_ * H_;
    float p = 0.f;
    for (int h = t; h < H_; h += 256) p += qp[h] * dp[h];
    s_red[t] = p;
    __syncthreads();
    for (int s = 128; s > 0; s >>= 1) {
        if (t < s) s_red[t] += s_red[t + s];
        __syncthreads();
    }

    if (t < 32) {
        float m = fmaxf(
            fmaxf(g_pmax[(b * 4 + 0) * LQ_ + t], g_pmax[(b * 4 + 1) * LQ_ + t]),
            fmaxf(g_pmax[(b * 4 + 2) * LQ_ + t], g_pmax[(b * 4 + 3) * LQ_ + t]));
        float term = qmask[b * LQ_ + t] ? m : 0.f;
#pragma unroll
        for (int o = 16; o >= 1; o >>= 1)
            term += __shfl_xor_sync(0xffffffffu, term, o);
        if (t == 0) {
            float w_  = 1.f / (1.f + expf(-merger[0]));
            float cls = s_red[0] * w_;
            float ts  = term * (1.f - w_);
            out[b]          = cls + ts;
            out[B_ + b]     = cls;
            out[2 * B_ + b] = ts;
        }
    }
}

extern "C" void kernel_launch(void* const* d_in, const int* in_sizes, int n_in,
                              void* d_out, int out_size)
{
    const float* query_hidden = (const float*)d_in[0];
    const float* doc_hidden   = (const float*)d_in[1];
    const int*   query_mask   = (const int*)  d_in[2];
    const int*   doc_mask     = (const int*)  d_in[3];
    const float* W_comp       = (const float*)d_in[4];
    const float* b_comp       = (const float*)d_in[5];
    const float* w_stop       = (const float*)d_in[6];
    const float* b_stop       = (const float*)d_in[7];
    const float* score_merger = (const float*)d_in[8];
    float* out = (float*)d_out;

    cudaFuncSetAttribute(gemm_tc<true>,
                         cudaFuncAttributeMaxDynamicSharedMemorySize, GEMM_SMEM);
    cudaFuncSetAttribute(gemm_tc<false>,
                         cudaFuncAttributeMaxDynamicSharedMemorySize, GEMM_SMEM);
    cudaFuncSetAttribute(score_partial,
                         cudaFuncAttributeMaxDynamicSharedMemorySize, SP_SMEM);

    prep_w<<<(H_ * C_ + 255) / 256, 256>>>(W_comp);
    gemm_tc<false><<<(B_ * LQ_) / 128, 256, GEMM_SMEM>>>(
        query_hidden, b_comp, w_stop, b_stop, query_mask);
    gemm_tc<true><<<(B_ * LD_) / 128, 256, GEMM_SMEM>>>(
        doc_hidden, b_comp, w_stop, b_stop, doc_mask);
    score_partial<<<B_ * 4, 256, SP_SMEM>>>(doc_mask);
    score_final<<<B_, 256>>>(
        query_hidden, doc_hidden, query_mask, score_merger, out);
}

// round 11
// speedup vs baseline: 6.2061x; 1.2595x over previous
#include <cuda_runtime.h>
#include <cuda_fp16.h>
#include <math.h>
#include <stdint.h>

#define B_  128
#define LQ_ 32
#define LD_ 512
#define H_  768
#define C_  128
#define KCH 32
#define NCH (H_ / KCH)   // 24 K-chunks
#define AP  36           // A [row][k] pad (fp32)
#define BPh 40           // B [col][k] pad (fp16)
#define STG 3            // cp.async pipeline stages
#define NSPL 8           // score split-K chunks (512/64)
#define KROWS 64         // k-rows per score_partial CTA
#define QBLK (B_ * LQ_ / 128)    // 32 query gemm blocks
#define DBLK (B_ * LD_ / 128)    // 512 doc gemm blocks

// Scratch (__device__ globals: allocation-free rule)
__device__ __half g_dvecs[B_ * LD_ * C_];   // 16.7 MB
__device__ __half g_qvecs[B_ * LQ_ * C_];   // 1 MB
__device__ __half g_Wth[C_ * H_];           // W_comp transposed, fp16
__device__ float  g_pmax[B_ * NSPL * LQ_];  // split-K partial maxima

__device__ __forceinline__ uint32_t smem_u32(const void* p) {
    uint32_t a;
    asm("{ .reg .u64 t; cvta.to.shared.u64 t, %1; cvt.u32.u64 %0, t; }"
        : "=r"(a) : "l"(p));
    return a;
}
__device__ __forceinline__ void cp16(void* dst, const void* src) {
    asm volatile("cp.async.cg.shared.global [%0], [%1], 16;"
                 :: "r"(smem_u32(dst)), "l"(src));
}
#define CP_COMMIT() asm volatile("cp.async.commit_group;" ::: "memory")
#define CP_WAIT1()  asm volatile("cp.async.wait_group 1;" ::: "memory")

__device__ __forceinline__ uint32_t h2u(float x, float y) {
    __half2 h = __floats2half2_rn(x, y);
    return *(uint32_t*)&h;
}

__device__ __forceinline__ void mma_f16(float c[4], uint32_t a0, uint32_t a1,
                                        uint32_t a2, uint32_t a3,
                                        uint32_t b0, uint32_t b1) {
    asm volatile(
        "mma.sync.aligned.m16n8k16.row.col.f32.f16.f16.f32 "
        "{%0,%1,%2,%3}, {%4,%5,%6,%7}, {%8,%9}, {%0,%1,%2,%3};"
        : "+f"(c[0]), "+f"(c[1]), "+f"(c[2]), "+f"(c[3])
        : "r"(a0), "r"(a1), "r"(a2), "r"(a3), "r"(b0), "r"(b1));
}

// ---------------------------------------------------------------------------
// Prep: transpose W_comp [H,C] -> g_Wth [C,H] (K-major), fp16
// ---------------------------------------------------------------------------
__global__ void prep_w(const float* __restrict__ W) {
    int idx = blockIdx.x * 256 + threadIdx.x;
    if (idx < H_ * C_) {
        int k = idx / C_, c = idx % C_;
        g_Wth[c * H_ + k] = __float2half_rn(W[idx]);
    }
}

// ---------------------------------------------------------------------------
// Merged projection GEMM (query blocks 0..31, doc blocks 32..543).
// 3-stage cp.async pipeline, mma.sync fp16, fp32 accum. 128x128 tile, K=768.
// Doc: fused importance gating + dm mask -> g_dvecs; query: qm -> g_qvecs.
// ---------------------------------------------------------------------------
#define A_BYTES (128 * AP * 4)
#define B_BYTES (128 * BPh * 2)
#define STAGE_BYTES (A_BYTES + B_BYTES)
#define GEMM_SMEM (STG * STAGE_BYTES)

__global__ void __launch_bounds__(256, 2) gemm_all(
    const float* __restrict__ Xq,
    const float* __restrict__ Xd,
    const float* __restrict__ bcomp,
    const float* __restrict__ wstop,
    const float* __restrict__ bstop,
    const int*   __restrict__ qmask,
    const int*   __restrict__ dmask)
{
    extern __shared__ char smg[];

    const bool isq = blockIdx.x < QBLK;
    const int  blk = isq ? blockIdx.x : blockIdx.x - QBLK;
    const float* X    = isq ? Xq : Xd;
    const int*   mask = isq ? qmask : dmask;

    const int t    = threadIdx.x;
    const int lane = t & 31;
    const int w    = t >> 5;
    const int wm   = w >> 1, wn = w & 1;
    const int g    = lane >> 2, tig = lane & 3;
    const int Rl   = wm * 32, Cl = wn * 64;
    const int row0 = blk * 128;

    // A staging: row = t>>3 (+32u), col quad = (t&7)*4 floats
    const int sar = t >> 3;
    const int sak = (t & 7) * 4;
    const float* Xp = X + (size_t)(row0 + sar) * H_ + sak;

    float acc[2][8][4];
#pragma unroll
    for (int mt = 0; mt < 2; mt++)
#pragma unroll
        for (int nt = 0; nt < 8; nt++)
#pragma unroll
            for (int x = 0; x < 4; x++) acc[mt][nt][x] = 0.f;

    // ---- prologue: stage chunks 0,1 ----
#pragma unroll
    for (int s = 0; s < 2; s++) {
        float*  As = (float*)(smg + s * STAGE_BYTES);
        __half* Bs = (__half*)(smg + s * STAGE_BYTES + A_BYTES);
        const int kt = s * KCH;
#pragma unroll
        for (int u = 0; u < 4; u++)
            cp16(&As[(sar + 32 * u) * AP + sak], Xp + (size_t)(32 * u) * H_ + kt);
#pragma unroll
        for (int u = 0; u < 2; u++) {
            int i  = t + u * 256;
            int cb = i >> 2;
            int k8 = (i & 3) * 8;
            cp16(&Bs[cb * BPh + k8], g_Wth + (size_t)cb * H_ + kt + k8);
        }
        CP_COMMIT();
    }

    int snext = 2;
    for (int ch = 0; ch < NCH; ch++) {
        CP_WAIT1();
        __syncthreads();

        if (ch + 2 < NCH) {
            float*  As = (float*)(smg + snext * STAGE_BYTES);
            __half* Bs = (__half*)(smg + snext * STAGE_BYTES + A_BYTES);
            const int kt = (ch + 2) * KCH;
#pragma unroll
            for (int u = 0; u < 4; u++)
                cp16(&As[(sar + 32 * u) * AP + sak],
                     Xp + (size_t)(32 * u) * H_ + kt);
#pragma unroll
            for (int u = 0; u < 2; u++) {
                int i  = t + u * 256;
                int cb = i >> 2;
                int k8 = (i & 3) * 8;
                cp16(&Bs[cb * BPh + k8], g_Wth + (size_t)cb * H_ + kt + k8);
            }
            CP_COMMIT();
            snext = (snext + 1 == STG) ? 0 : snext + 1;
        } else {
            CP_COMMIT();
        }

        const int sc = ch % STG;
        const float*  As = (const float*)(smg + sc * STAGE_BYTES);
        const __half* Bs = (const __half*)(smg + sc * STAGE_BYTES + A_BYTES);

#pragma unroll
        for (int ks = 0; ks < 2; ks++) {
            const int k0 = ks * 16;
            uint32_t a[2][4];
#pragma unroll
            for (int mt = 0; mt < 2; mt++) {
                int r = Rl + mt * 16 + g;
                float2 f0 = *(const float2*)&As[r * AP + k0 + 2 * tig];
                float2 f1 = *(const float2*)&As[(r + 8) * AP + k0 + 2 * tig];
                float2 f2 = *(const float2*)&As[r * AP + k0 + 8 + 2 * tig];
                float2 f3 = *(const float2*)&As[(r + 8) * AP + k0 + 8 + 2 * tig];
                a[mt][0] = h2u(f0.x, f0.y);
                a[mt][1] = h2u(f1.x, f1.y);
                a[mt][2] = h2u(f2.x, f2.y);
                a[mt][3] = h2u(f3.x, f3.y);
            }
#pragma unroll
            for (int nt = 0; nt < 8; nt++) {
                int c = Cl + nt * 8 + g;
                uint32_t b0 = *(const uint32_t*)&Bs[c * BPh + k0 + 2 * tig];
                uint32_t b1 = *(const uint32_t*)&Bs[c * BPh + k0 + 8 + 2 * tig];
                mma_f16(acc[0][nt], a[0][0], a[0][1], a[0][2], a[0][3], b0, b1);
                mma_f16(acc[1][nt], a[1][0], a[1][1], a[1][2], a[1][3], b0, b1);
            }
        }
    }
    __syncthreads();

    // ---- Epilogue ----
    float bb[8][2];
#pragma unroll
    for (int nt = 0; nt < 8; nt++) {
        int c0 = Cl + nt * 8 + 2 * tig;
        bb[nt][0] = bcomp[c0];
        bb[nt][1] = bcomp[c0 + 1];
    }

    float (*spart)[2] = (float(*)[2])smg;        // 128 x 2 partials
    float* sscale     = (float*)smg + 256;       // 128 scales

    if (!isq) {
        float ws[8][2];
#pragma unroll
        for (int nt = 0; nt < 8; nt++) {
            int c0 = Cl + nt * 8 + 2 * tig;
            ws[nt][0] = wstop[c0];
            ws[nt][1] = wstop[c0 + 1];
        }
        float p[2][2] = {{0.f, 0.f}, {0.f, 0.f}};
#pragma unroll
        for (int mt = 0; mt < 2; mt++)
#pragma unroll
            for (int nt = 0; nt < 8; nt++) {
                p[mt][0] += (acc[mt][nt][0] + bb[nt][0]) * ws[nt][0]
                          + (acc[mt][nt][1] + bb[nt][1]) * ws[nt][1];
                p[mt][1] += (acc[mt][nt][2] + bb[nt][0]) * ws[nt][0]
                          + (acc[mt][nt][3] + bb[nt][1]) * ws[nt][1];
            }
#pragma unroll
        for (int mt = 0; mt < 2; mt++)
#pragma unroll
            for (int h = 0; h < 2; h++) {
                float v = p[mt][h];
                v += __shfl_xor_sync(0xffffffffu, v, 1);
                v += __shfl_xor_sync(0xffffffffu, v, 2);
                p[mt][h] = v;
            }
        if (tig == 0) {
#pragma unroll
            for (int mt = 0; mt < 2; mt++)
#pragma unroll
                for (int h = 0; h < 2; h++)
                    spart[Rl + mt * 16 + g + 8 * h][wn] = p[mt][h];
        }
        __syncthreads();
        if (t < 128) {
            float pp = spart[t][0] + spart[t][1] + bstop[0];
            sscale[t] = fmaxf(pp, 0.f) * (float)mask[row0 + t];
        }
        __syncthreads();
    } else {
        if (t < 128) sscale[t] = (float)mask[row0 + t];
        __syncthreads();
    }

    __half* OUT = isq ? g_qvecs : g_dvecs;
#pragma unroll
    for (int mt = 0; mt < 2; mt++)
#pragma unroll
        for (int h = 0; h < 2; h++) {
            int lrow = Rl + mt * 16 + g + 8 * h;
            float s  = sscale[lrow];
            int row  = row0 + lrow;
#pragma unroll
            for (int nt = 0; nt < 8; nt++) {
                int c0 = Cl + nt * 8 + 2 * tig;
                uint32_t hv = h2u((acc[mt][nt][2 * h + 0] + bb[nt][0]) * s,
                                  (acc[mt][nt][2 * h + 1] + bb[nt][1]) * s);
                *(uint32_t*)(OUT + (size_t)row * C_ + c0) = hv;
            }
        }
}

// ---------------------------------------------------------------------------
// Split-K scoring stage 1 (fp16 mma): CTA (b, ci) computes masked max over
// 64 k-rows: q_vecs[b] @ d_vecs[b, ci*64 : +64]^T -> g_pmax[b][ci][32]
// 8 warps: wq = q half (16 rows), wk = k group (16 rows of the 64).
// smem tail: redm = 32 q-rows x 4 k-groups (128 floats), dmch = KROWS ints.
// ---------------------------------------------------------------------------
#define QPh 136
#define SP_SMEM ((32 * QPh + KROWS * QPh) * 2 + 128 * 4 + KROWS * 4)

__global__ void __launch_bounds__(256) score_partial(
    const int* __restrict__ dmask)
{
    extern __shared__ char smc[];
    __half* qs   = (__half*)smc;                        // 32 * QPh
    __half* ds   = qs + 32 * QPh;                       // KROWS * QPh
    float*  redm = (float*)(ds + KROWS * QPh);          // 128 floats
    int*    dmch = (int*)(redm + 128);                  // KROWS ints

    const int b    = blockIdx.x >> 3;
    const int ci   = blockIdx.x & 7;
    const int k0g  = ci * KROWS;
    const int t    = threadIdx.x;
    const int lane = t & 31;
    const int w    = t >> 5;
    const int g    = lane >> 2, tig = lane & 3;
    const int wq   = w & 1;    // q half (16 rows)
    const int wk   = w >> 1;   // k group (16 rows)

    // Stage q_vecs [32 x 128] fp16 (512 x 8 halfs)
#pragma unroll
    for (int u = 0; u < 2; u++) {
        int i  = t + u * 256;
        int q  = i >> 4;
        int c8 = (i & 15) * 8;
        *(uint4*)&qs[q * QPh + c8] = *(const uint4*)(
            g_qvecs + (size_t)b * LQ_ * C_ + (size_t)q * C_ + c8);
    }
    // Stage d chunk [64 x 128] fp16 (1024 x 8 halfs)
#pragma unroll
    for (int u = 0; u < 4; u++) {
        int i  = t + u * 256;
        int k  = i >> 4;
        int c8 = (i & 15) * 8;
        *(uint4*)&ds[k * QPh + c8] = *(const uint4*)(
            g_dvecs + (size_t)b * LD_ * C_ + (size_t)(k0g + k) * C_ + c8);
    }
    if (t < KROWS) dmch[t] = dmask[b * LD_ + k0g + t];
    __syncthreads();

    float acc[2][4];
#pragma unroll
    for (int nt = 0; nt < 2; nt++)
#pragma unroll
        for (int x = 0; x < 4; x++) acc[nt][x] = 0.f;

#pragma unroll
    for (int cs = 0; cs < 8; cs++) {
        const int c0 = cs * 16;
        uint32_t a0 = *(const uint32_t*)&qs[(wq * 16 + g) * QPh + c0 + 2 * tig];
        uint32_t a1 = *(const uint32_t*)&qs[(wq * 16 + g + 8) * QPh + c0 + 2 * tig];
        uint32_t a2 = *(const uint32_t*)&qs[(wq * 16 + g) * QPh + c0 + 8 + 2 * tig];
        uint32_t a3 = *(const uint32_t*)&qs[(wq * 16 + g + 8) * QPh + c0 + 8 + 2 * tig];
#pragma unroll
        for (int nt = 0; nt < 2; nt++) {
            int n = wk * 16 + nt * 8 + g;
            uint32_t b0 = *(const uint32_t*)&ds[n * QPh + c0 + 2 * tig];
            uint32_t b1 = *(const uint32_t*)&ds[n * QPh + c0 + 8 + 2 * tig];
            mma_f16(acc[nt], a0, a1, a2, a3, b0, b1);
        }
    }

    float mx0 = -1000.f, mx1 = -1000.f;
#pragma unroll
    for (int nt = 0; nt < 2; nt++) {
        int n0 = wk * 16 + nt * 8 + 2 * tig;
        if (dmch[n0]) {
            mx0 = fmaxf(mx0, acc[nt][0]);
            mx1 = fmaxf(mx1, acc[nt][2]);
        }
        if (dmch[n0 + 1]) {
            mx0 = fmaxf(mx0, acc[nt][1]);
            mx1 = fmaxf(mx1, acc[nt][3]);
        }
    }
    mx0 = fmaxf(mx0, __shfl_xor_sync(0xffffffffu, mx0, 1));
    mx0 = fmaxf(mx0, __shfl_xor_sync(0xffffffffu, mx0, 2));
    mx1 = fmaxf(mx1, __shfl_xor_sync(0xffffffffu, mx1, 1));
    mx1 = fmaxf(mx1, __shfl_xor_sync(0xffffffffu, mx1, 2));
    __syncthreads();
    if (tig == 0) {
        redm[(wq * 16 + g) * 4 + wk]     = mx0;
        redm[(wq * 16 + g + 8) * 4 + wk] = mx1;
    }
    __syncthreads();

    if (t < 32) {
        float m = fmaxf(fmaxf(redm[t * 4 + 0], redm[t * 4 + 1]),
                        fmaxf(redm[t * 4 + 2], redm[t * 4 + 3]));
        g_pmax[(b * NSPL + ci) * LQ_ + t] = m;
    }
}

// ---------------------------------------------------------------------------
// Split-K scoring stage 2: CLS dot + merge of NSPL partial maxima per batch
// ---------------------------------------------------------------------------
__global__ void __launch_bounds__(256) score_final(
    const float* __restrict__ qh,
    const float* __restrict__ dhid,
    const int*   __restrict__ qmask,
    const float* __restrict__ merger,
    float*       __restrict__ out)
{
    __shared__ float s_red[256];

    const int b = blockIdx.x;
    const int t = threadIdx.x;

    const float* qp = qh   + (size_t)b * LQ_ * H_;
    const float* dp = dhid + (size_t)b * LD_ * H_;
    float p = 0.f;
    for (int h = t; h < H_; h += 256) p += qp[h] * dp[h];
    s_red[t] = p;
    __syncthreads();
    for (int s = 128; s > 0; s >>= 1) {
        if (t < s) s_red[t] += s_red[t + s];
        __syncthreads();
    }

    if (t < 32) {
        float m = -1000.f;
#pragma unroll
        for (int ci = 0; ci < NSPL; ci++)
            m = fmaxf(m, g_pmax[(b * NSPL + ci) * LQ_ + t]);
        float term = qmask[b * LQ_ + t] ? m : 0.f;
#pragma unroll
        for (int o = 16; o >= 1; o >>= 1)
            term += __shfl_xor_sync(0xffffffffu, term, o);
        if (t == 0) {
            float w_  = 1.f / (1.f + expf(-merger[0]));
            float cls = s_red[0] * w_;
            float ts  = term * (1.f - w_);
            out[b]          = cls + ts;
            out[B_ + b]     = cls;
            out[2 * B_ + b] = ts;
        }
    }
}

extern "C" void kernel_launch(void* const* d_in, const int* in_sizes, int n_in,
                              void* d_out, int out_size)
{
    const float* query_hidden = (const float*)d_in[0];
    const float* doc_hidden   = (const float*)d_in[1];
    const int*   query_mask   = (const int*)  d_in[2];
    const int*   doc_mask     = (const int*)  d_in[3];
    const float* W_comp       = (const float*)d_in[4];
    const float* b_comp       = (const float*)d_in[5];
    const float* w_stop       = (const float*)d_in[6];
    const float* b_stop       = (const float*)d_in[7];
    const float* score_merger = (const float*)d_in[8];
    float* out = (float*)d_out;

    cudaFuncSetAttribute(gemm_all,
                         cudaFuncAttributeMaxDynamicSharedMemorySize, GEMM_SMEM);
    cudaFuncSetAttribute(score_partial,
                         cudaFuncAttributeMaxDynamicSharedMemorySize, SP_SMEM);

    prep_w<<<(H_ * C_ + 255) / 256, 256>>>(W_comp);
    gemm_all<<<QBLK + DBLK, 256, GEMM_SMEM>>>(
        query_hidden, doc_hidden, b_comp, w_stop, b_stop,
        query_mask, doc_mask);
    score_partial<<<B_ * NSPL, 256, SP_SMEM>>>(doc_mask);
    score_final<<<B_, 256>>>(
        query_hidden, doc_hidden, query_mask, score_merger, out);
}